// round 6
// baseline (speedup 1.0000x reference)
#include <cuda_runtime.h>
#include <cuda_bf16.h>
#include <cstdint>

#define NROW 2048
#define DM   1152
#define SKV  256
#define HIDN 768
#define REG  288   // DM/4

// ---------------- scratch (device globals; allocation-free) ----------------
__device__ float g_q[NROW*DM];
__device__ float g_k[SKV*DM];
__device__ float g_v[SKV*DM];
__device__ float g_ca[NROW*DM];
__device__ float g_cap2[NROW*DM];
__device__ float g_caplog[NROW*4];
__device__ float g_aclog[NROW*4];
__device__ float g_hl[4];
__device__ float g_cm[NROW];
__device__ float g_am[NROW];
__device__ int   g_cpe[NROW];
__device__ int   g_ape[NROW];
__device__ int   g_cnt[8];
__device__ int   g_off[8];
__device__ int   g_cur[8];
__device__ int   g_idx[2*NROW];
__device__ float g_H1[NROW*HIDN];
__device__ float g_H3[NROW*HIDN];
__device__ float g_H [NROW*HIDN];
__device__ float g_R1[4L*NROW*HIDN];
__device__ float g_R3[4L*NROW*HIDN];
__device__ float g_R [4L*NROW*HIDN];
__device__ float g_y[NROW*DM];

// ---------------- threefry2x32-20 (exact JAX, partitionable) ----------------
__device__ __forceinline__ uint32_t rotl32(uint32_t v, int r){ return (v<<r)|(v>>(32-r)); }

__device__ __forceinline__ void tf2x32(uint32_t k0, uint32_t k1, uint32_t x0, uint32_t x1,
                                       uint32_t& o0, uint32_t& o1)
{
    uint32_t ks2 = k0 ^ k1 ^ 0x1BD11BDAu;
    x0 += k0; x1 += k1;
#define TFR(r) { x0 += x1; x1 = rotl32(x1,(r)); x1 ^= x0; }
    TFR(13) TFR(15) TFR(26) TFR(6)   x0 += k1;  x1 += ks2 + 1u;
    TFR(17) TFR(29) TFR(16) TFR(24)  x0 += ks2; x1 += k0  + 2u;
    TFR(13) TFR(15) TFR(26) TFR(6)   x0 += k0;  x1 += k1  + 3u;
    TFR(17) TFR(29) TFR(16) TFR(24)  x0 += k1;  x1 += ks2 + 4u;
    TFR(13) TFR(15) TFR(26) TFR(6)   x0 += ks2; x1 += k0  + 5u;
#undef TFR
    o0 = x0; o1 = x1;
}

__device__ __forceinline__ uint32_t jax_bits_p(uint32_t k0, uint32_t k1, uint32_t i)
{
    uint32_t o0, o1;
    tf2x32(k0, k1, 0u, i, o0, o1);
    return o0 ^ o1;
}

__device__ __forceinline__ float gumbel_from_bits(uint32_t bits)
{
    uint32_t fb = (bits >> 9) | 0x3f800000u;
    float f = __uint_as_float(fb) - 1.0f;
    const float TINY = 1.17549435e-38f;
    float u = (f > 0.0f) ? f : TINY;
    return -logf(-logf(u));
}

// ---------------- bf16-split tensor-core GEMM (3-term compensated) ----------
// C[gr][n] = sum_k A[gr][k] * W[n][k]
// Block tile 128(M) x 64(N) x 32(K); 128 threads (4 warps, warp tile 64x32).
// Split a = ahi + alo (RN bf16 twice), same for b, at LOAD time.
// D += ahi*bhi + ahi*blo + alo*bhi via mma.m16n8k16.bf16 (err ~1e-5 rel).
// GATHER: rows indirected via per-expert buckets. EPI: 0 store(+bias),
// 1 store*rowScale[gr], 2 += *rowScale[gr].

__device__ __forceinline__ void mma16(float* d, const uint32_t* a, const uint32_t* b)
{
    asm volatile(
        "mma.sync.aligned.m16n8k16.row.col.f32.bf16.bf16.f32 "
        "{%0,%1,%2,%3}, {%4,%5,%6,%7}, {%8,%9}, {%0,%1,%2,%3};\n"
        : "+f"(d[0]), "+f"(d[1]), "+f"(d[2]), "+f"(d[3])
        : "r"(a[0]), "r"(a[1]), "r"(a[2]), "r"(a[3]), "r"(b[0]), "r"(b[1]));
}

__device__ __forceinline__ void split2(float f0, float f1, uint32_t& hi, uint32_t& lo)
{
    __nv_bfloat162 h = __floats2bfloat162_rn(f0, f1);
    float r0 = f0 - __bfloat162float(h.x);
    float r1 = f1 - __bfloat162float(h.y);
    __nv_bfloat162 l = __floats2bfloat162_rn(r0, r1);
    hi = *(uint32_t*)&h;
    lo = *(uint32_t*)&l;
}

#define LDA32 136   // A: [k2=16][LDA32] uint32 (bf16x2 along k), per stage
#define LDB32 20    // B: [n=64][LDB32] uint32, per stage
#define A_ST  (16*LDA32)
#define B_ST  (64*LDB32)
// u32 layout: AsH[2*A_ST] AsL[2*A_ST] BsH[2*B_ST] BsL[2*B_ST] rmap[128]
#define SMEM_GEMM ((4*A_ST + 4*B_ST + 128)*4)

template<int GATHER, int EPI>
__global__ __launch_bounds__(128)
void gemm_tc(const float* __restrict__ A, int lda, long long aOff,
             const float* __restrict__ W, int ldw, long long wOff,
             const float* __restrict__ bias,
             float* __restrict__ C, int ldc, long long cOff,
             const int* __restrict__ rowIdx, const int* __restrict__ bOff,
             const int* __restrict__ bCnt, int bBase,
             const float* __restrict__ rowScale,
             int M, int N, int K)
{
    extern __shared__ uint32_t smu[];
    uint32_t* AsH = smu;
    uint32_t* AsL = smu + 2*A_ST;
    uint32_t* BsH = smu + 4*A_ST;
    uint32_t* BsL = smu + 4*A_ST + 2*B_ST;
    int* rmap = (int*)(smu + 4*A_ST + 4*B_ST);

    const int e = blockIdx.z;
    A += (long long)e * aOff;
    W += (long long)e * wOff;
    C += (long long)e * cOff;
    int rows = M; const int* idx = nullptr;
    if (GATHER) { rows = bCnt[bBase+e]; idx = rowIdx + bOff[bBase+e]; }
    const int m0 = blockIdx.y * 128, n0 = blockIdx.x * 64;
    if (m0 >= rows) return;

    const int tid = threadIdx.x;
    const int warp = tid >> 5, lane = tid & 31;
    const int wm = warp >> 1, wn = warp & 1;
    const int g = lane >> 2, tq = lane & 3;

    {
        int r = m0 + tid;
        rmap[tid] = (r < rows) ? (GATHER ? idx[r] : r) : -1;
    }
    __syncthreads();

    const int agr = rmap[tid];
    const float* arow = (agr >= 0) ? (A + (long long)agr * lda) : nullptr;
    const int bn = tid & 63;
    const int bkh = tid >> 6;
    const bool bvalid = (n0 + bn) < N;
    const float* brow = bvalid ? (W + (long long)(n0 + bn) * ldw + bkh * 16) : nullptr;

    float4 ra[8], rb[4];
    float d[4][4][4];
    #pragma unroll
    for (int i = 0; i < 4; i++)
        #pragma unroll
        for (int j = 0; j < 4; j++)
            #pragma unroll
            for (int r = 0; r < 4; r++) d[i][j][r] = 0.f;

    const float4 z4 = make_float4(0.f,0.f,0.f,0.f);

#define LOADT(k0) { \
    _Pragma("unroll") \
    for (int l = 0; l < 8; l++) ra[l] = arow ? *(const float4*)(arow + (k0) + l*4) : z4; \
    _Pragma("unroll") \
    for (int l = 0; l < 4; l++) rb[l] = brow ? *(const float4*)(brow + (k0) + l*4) : z4; \
    }

#define STORET(buf) { \
    uint32_t* ah = AsH + (buf)*A_ST; \
    uint32_t* al = AsL + (buf)*A_ST; \
    _Pragma("unroll") \
    for (int l = 0; l < 8; l++) { \
        uint32_t h0,l0,h1,l1; \
        split2(ra[l].x, ra[l].y, h0, l0); \
        split2(ra[l].z, ra[l].w, h1, l1); \
        ah[(2*l+0)*LDA32 + tid] = h0; al[(2*l+0)*LDA32 + tid] = l0; \
        ah[(2*l+1)*LDA32 + tid] = h1; al[(2*l+1)*LDA32 + tid] = l1; \
    } \
    uint32_t* bh = BsH + (buf)*B_ST + bn*LDB32 + bkh*8; \
    uint32_t* bl = BsL + (buf)*B_ST + bn*LDB32 + bkh*8; \
    _Pragma("unroll") \
    for (int l = 0; l < 4; l++) { \
        uint32_t h0,l0,h1,l1; \
        split2(rb[l].x, rb[l].y, h0, l0); \
        split2(rb[l].z, rb[l].w, h1, l1); \
        bh[2*l+0] = h0; bl[2*l+0] = l0; \
        bh[2*l+1] = h1; bl[2*l+1] = l1; \
    } }

#define COMPUTET(buf) { \
    const uint32_t* ah = AsH + (buf)*A_ST; \
    const uint32_t* al = AsL + (buf)*A_ST; \
    const uint32_t* bh = BsH + (buf)*B_ST; \
    const uint32_t* bl = BsL + (buf)*B_ST; \
    _Pragma("unroll") \
    for (int kc = 0; kc < 2; kc++) { \
        int kp = kc*8 + tq; \
        uint32_t bhi[4][2], blo[4][2]; \
        _Pragma("unroll") \
        for (int nt = 0; nt < 4; nt++) { \
            int n = wn*32 + nt*8 + g; \
            bhi[nt][0] = bh[n*LDB32 + kp];     bhi[nt][1] = bh[n*LDB32 + kp + 4]; \
            blo[nt][0] = bl[n*LDB32 + kp];     blo[nt][1] = bl[n*LDB32 + kp + 4]; \
        } \
        _Pragma("unroll") \
        for (int mt = 0; mt < 4; mt++) { \
            int mg = wm*64 + mt*16 + g; \
            uint32_t ahi[4], alo[4]; \
            ahi[0] = ah[kp*LDA32 + mg];       ahi[1] = ah[kp*LDA32 + mg + 8]; \
            ahi[2] = ah[(kp+4)*LDA32 + mg];   ahi[3] = ah[(kp+4)*LDA32 + mg + 8]; \
            alo[0] = al[kp*LDA32 + mg];       alo[1] = al[kp*LDA32 + mg + 8]; \
            alo[2] = al[(kp+4)*LDA32 + mg];   alo[3] = al[(kp+4)*LDA32 + mg + 8]; \
            _Pragma("unroll") \
            for (int nt = 0; nt < 4; nt++) { \
                mma16(d[mt][nt], ahi, bhi[nt]); \
                mma16(d[mt][nt], ahi, blo[nt]); \
                mma16(d[mt][nt], alo, bhi[nt]); \
            } \
        } \
    } }

    LOADT(0)
    STORET(0)
    __syncthreads();
    int buf = 0;
    for (int k0 = 32; k0 < K; k0 += 32) {
        LOADT(k0)
        COMPUTET(buf)
        STORET(buf^1)
        __syncthreads();
        buf ^= 1;
    }
    COMPUTET(buf)

#undef LOADT
#undef STORET
#undef COMPUTET

    // epilogue (m16n8k16 C layout == m16n8k8: d0,d1 row g; d2,d3 row g+8)
    #pragma unroll
    for (int mt = 0; mt < 4; mt++) {
        #pragma unroll
        for (int h = 0; h < 2; h++) {
            int r = wm*64 + mt*16 + g + 8*h;
            int gr = rmap[r];
            if (gr < 0) continue;
            float* crow = C + (long long)gr * ldc;
            float sc = (EPI >= 1) ? rowScale[gr] : 0.f;
            #pragma unroll
            for (int nt = 0; nt < 4; nt++) {
                int c0 = n0 + wn*32 + nt*8 + tq*2;
                if (c0 >= N) continue;
                float v0 = d[mt][nt][h*2+0];
                float v1 = d[mt][nt][h*2+1];
                if (EPI == 0) {
                    if (bias) { v0 += bias[c0]; v1 += bias[c0+1]; }
                    *(float2*)(crow + c0) = make_float2(v0, v1);
                } else if (EPI == 1) {
                    *(float2*)(crow + c0) = make_float2(v0*sc, v1*sc);
                } else {
                    float2 old = *(float2*)(crow + c0);
                    *(float2*)(crow + c0) = make_float2(old.x + v0*sc, old.y + v1*sc);
                }
            }
        }
    }
}

// ---------------- attention: 64 queries x (head,batch) per block ------------
#define SMEM_ATTN 220160

__global__ __launch_bounds__(256)
void attn2(const float* __restrict__ Q, const float* __restrict__ K,
           const float* __restrict__ V, float* __restrict__ O)
{
    extern __shared__ float smatt[];
    float* Qs = smatt;
    float* Ks = smatt + 144*64;
    float* Vs = smatt + 144*64 + 144*128;
    float* Ss = Vs + 128*148;

    const int tid = threadIdx.x;
    const int q0 = blockIdx.x * 64;
    const int h = blockIdx.y, b = blockIdx.z;
    const long long qrow0 = (long long)b*1024 + q0;
    const int hc = h*144;

    for (int i = tid; i < 64*36; i += 256) {
        int q = i / 36, f = i % 36;
        float4 v4 = *(const float4*)(Q + (qrow0 + q)*DM + hc + f*4);
        Qs[(f*4+0)*64+q]=v4.x; Qs[(f*4+1)*64+q]=v4.y;
        Qs[(f*4+2)*64+q]=v4.z; Qs[(f*4+3)*64+q]=v4.w;
    }
    for (int i = tid; i < 128*36; i += 256) {
        int k = i / 36, f = i % 36;
        float4 v4 = *(const float4*)(K + ((long long)b*128 + k)*DM + hc + f*4);
        Ks[(f*4+0)*128+k]=v4.x; Ks[(f*4+1)*128+k]=v4.y;
        Ks[(f*4+2)*128+k]=v4.z; Ks[(f*4+3)*128+k]=v4.w;
        float4 w4 = *(const float4*)(V + ((long long)b*128 + k)*DM + hc + f*4);
        *(float4*)&Vs[k*148 + f*4] = w4;
    }
    __syncthreads();

    const int tx = tid & 15, ty = tid >> 4;

    {
        float acc[4][8] = {};
        for (int d = 0; d < 144; d++) {
            float a[4], bv[8];
            *(float4*)a      = *(const float4*)&Qs[d*64 + ty*4];
            *(float4*)bv     = *(const float4*)&Ks[d*128 + tx*8];
            *(float4*)(bv+4) = *(const float4*)&Ks[d*128 + tx*8 + 4];
            #pragma unroll
            for (int i = 0; i < 4; i++)
                #pragma unroll
                for (int j = 0; j < 8; j++) acc[i][j] += a[i]*bv[j];
        }
        #pragma unroll
        for (int i = 0; i < 4; i++)
            #pragma unroll
            for (int j = 0; j < 8; j++)
                Ss[(ty*4+i)*132 + tx*8 + j] = acc[i][j] * (1.0f/12.0f);
    }
    __syncthreads();

    if (tid < 64) {
        float* r = Ss + tid*132;
        float mx = -1e30f;
        for (int k = 0; k < 128; k++) mx = fmaxf(mx, r[k]);
        float sum = 0.f;
        for (int k = 0; k < 128; k++) { float ev = expf(r[k]-mx); r[k] = ev; sum += ev; }
        float inv = 1.0f / sum;
        for (int k = 0; k < 128; k++) r[k] *= inv;
    }
    __syncthreads();

    {
        float o[4][9] = {};
        for (int k = 0; k < 128; k++) {
            float s[4];
            #pragma unroll
            for (int i = 0; i < 4; i++) s[i] = Ss[(ty*4+i)*132 + k];
            #pragma unroll
            for (int j = 0; j < 9; j++) {
                float vv = Vs[k*148 + tx*9 + j];
                #pragma unroll
                for (int i = 0; i < 4; i++) o[i][j] += s[i]*vv;
            }
        }
        #pragma unroll
        for (int i = 0; i < 4; i++)
            #pragma unroll
            for (int j = 0; j < 9; j++)
                O[(qrow0 + ty*4 + i)*DM + hc + tx*9 + j] = o[i][j];
    }
}

// ---------------- small kernels ----------------
__global__ void silumul4(const float4* __restrict__ H1, const float4* __restrict__ H3,
                         float4* __restrict__ Hout, int n4)
{
    int i = blockIdx.x*blockDim.x + threadIdx.x;
    if (i >= n4) return;
    float4 a = H1[i], c = H3[i], r;
    r.x = a.x/(1.f+expf(-a.x))*c.x;
    r.y = a.y/(1.f+expf(-a.y))*c.y;
    r.z = a.z/(1.f+expf(-a.z))*c.z;
    r.w = a.w/(1.f+expf(-a.w))*c.w;
    Hout[i] = r;
}

__global__ void gate4(const float* __restrict__ A, const float* __restrict__ W,
                      const float* __restrict__ b, float* __restrict__ out)
{
    int w = blockIdx.x*8 + (threadIdx.x >> 5);
    int lane = threadIdx.x & 31;
    if (w >= NROW) return;
    const float* a = A + (long long)w*DM;
    float s0=0,s1=0,s2=0,s3=0;
    for (int c = lane*4; c < DM; c += 128) {
        float4 av = *(const float4*)(a + c);
        float4 w0 = *(const float4*)(W + c);
        float4 w1 = *(const float4*)(W + DM + c);
        float4 w2 = *(const float4*)(W + 2*DM + c);
        float4 w3 = *(const float4*)(W + 3*DM + c);
        s0 += av.x*w0.x + av.y*w0.y + av.z*w0.z + av.w*w0.w;
        s1 += av.x*w1.x + av.y*w1.y + av.z*w1.z + av.w*w1.w;
        s2 += av.x*w2.x + av.y*w2.y + av.z*w2.z + av.w*w2.w;
        s3 += av.x*w3.x + av.y*w3.y + av.z*w3.z + av.w*w3.w;
    }
    #pragma unroll
    for (int o = 16; o > 0; o >>= 1) {
        s0 += __shfl_xor_sync(0xffffffffu, s0, o);
        s1 += __shfl_xor_sync(0xffffffffu, s1, o);
        s2 += __shfl_xor_sync(0xffffffffu, s2, o);
        s3 += __shfl_xor_sync(0xffffffffu, s3, o);
    }
    if (lane == 0) {
        out[w*4+0] = s0 + b[0]; out[w*4+1] = s1 + b[1];
        out[w*4+2] = s2 + b[2]; out[w*4+3] = s3 + b[3];
    }
}

__global__ void hlk(const float* __restrict__ t, const float* __restrict__ w,
                    const float* __restrict__ bb, float* __restrict__ hl)
{
    int wi = threadIdx.x >> 5, lane = threadIdx.x & 31;
    int r = wi >> 1, o = wi & 1;
    const float* a = t + r*DM;
    const float* ww = w + o*DM;
    float s = 0.f;
    for (int c = lane*4; c < DM; c += 128) {
        float4 av = *(const float4*)(a + c);
        float4 wv = *(const float4*)(ww + c);
        s += av.x*wv.x + av.y*wv.y + av.z*wv.z + av.w*wv.w;
    }
    #pragma unroll
    for (int off = 16; off > 0; off >>= 1) s += __shfl_xor_sync(0xffffffffu, s, off);
    if (lane == 0) hl[r*2+o] = s + bb[o];
}

// ---------------- gating + routing ----------------
__global__ void init_counts()
{
    if (threadIdx.x < 8) g_cnt[threadIdx.x] = 0;
}

__global__ void gating_kernel(const float* __restrict__ caplog, const float* __restrict__ aclog)
{
    int n = blockIdx.x * blockDim.x + threadIdx.x;
    if (n >= NROW) return;

    uint32_t k1a,k1b,k2a,k2b,k3a,k3b;
    tf2x32(0u, 42u, 0u, 0u, k1a, k1b);
    tf2x32(0u, 42u, 0u, 1u, k2a, k2b);
    tf2x32(0u, 42u, 0u, 2u, k3a, k3b);

    float g0 = gumbel_from_bits(jax_bits_p(k1a, k1b, 2u*(uint32_t)n + 0u));
    float g1 = gumbel_from_bits(jax_bits_p(k1a, k1b, 2u*(uint32_t)n + 1u));
    int bb = n >> 10;
    float l0 = g_hl[2*bb + 0] + g0;
    float l1 = g_hl[2*bb + 1] + g1;
    float mx = fmaxf(l0, l1);
    float e0 = expf(l0 - mx), e1 = expf(l1 - mx);
    float inv = 1.0f / (e0 + e1);
    g_cm[n] = e0 * inv;
    g_am[n] = e1 * inv;

    int be = 0; float bv = -1e30f;
    #pragma unroll
    for (int c = 0; c < 4; c++) {
        float g = gumbel_from_bits(jax_bits_p(k2a, k2b, 4u*(uint32_t)n + (uint32_t)c));
        float yv = caplog[n*4 + c] + g;
        if (yv > bv) { bv = yv; be = c; }
    }
    g_cpe[n] = be;
    atomicAdd(&g_cnt[be], 1);

    int ae = 0; bv = -1e30f;
    #pragma unroll
    for (int c = 0; c < 4; c++) {
        float g = gumbel_from_bits(jax_bits_p(k3a, k3b, 4u*(uint32_t)n + (uint32_t)c));
        float yv = aclog[n*4 + c] + g;
        if (yv > bv) { bv = yv; ae = c; }
    }
    g_ape[n] = ae;
    atomicAdd(&g_cnt[4 + ae], 1);
}

__global__ void offsets_kernel()
{
    int o = 0;
    for (int e = 0; e < 4; e++) { g_off[e] = o; o += g_cnt[e]; }
    o = NROW;
    for (int e = 4; e < 8; e++) { g_off[e] = o; o += g_cnt[e]; }
    for (int j = 0; j < 8; j++) g_cur[j] = g_off[j];
}

__global__ void scatter_kernel()
{
    int n = blockIdx.x * blockDim.x + threadIdx.x;
    if (n >= NROW) return;
    int e = g_cpe[n];
    int p = atomicAdd(&g_cur[e], 1);
    g_idx[p] = n;
    int a = g_ape[n];
    p = atomicAdd(&g_cur[4 + a], 1);
    g_idx[p] = n;
}

// ---------------- lb loss ----------------
__global__ void lb_kernel(float* __restrict__ outp, long long i1)
{
    __shared__ float sh[256 * 9];
    int t = threadIdx.x;
    float u[8] = {0,0,0,0,0,0,0,0};
    float ms = 0.f;
    for (int n = t; n < NROW; n += 256) {
        u[g_cpe[n]]     += g_cm[n];
        u[4 + g_ape[n]] += g_am[n];
        ms += g_cm[n] + g_am[n];
    }
    #pragma unroll
    for (int j = 0; j < 8; j++) sh[t*9 + j] = u[j];
    sh[t*9 + 8] = ms;
    __syncthreads();
    for (int stride = 128; stride > 0; stride >>= 1) {
        if (t < stride)
            #pragma unroll
            for (int j = 0; j < 9; j++) sh[t*9 + j] += sh[(t + stride)*9 + j];
        __syncthreads();
    }
    if (t == 0 && i1 >= 0) {
        float denom = 4.0f * sh[8] + 1e-10f;
        float acc = 0.f;
        for (int j = 0; j < 8; j++) {
            float uu = sh[j] / denom;
            acc += uu * logf(uu + 1e-10f);
        }
        outp[i1] = acc / 8.0f;
    }
}

// ---------------- host launcher ----------------
extern "C" void kernel_launch(void* const* d_in, const int* in_sizes, int n_in,
                              void* d_out, int out_size)
{
    const float* x        = (const float*)d_in[0];
    const float* timei    = (const float*)d_in[1];
    const float* caption  = (const float*)d_in[2];
    const float* acoustic = (const float*)d_in[3];
    const float* w_in     = (const float*)d_in[4];
    const float* b_in     = (const float*)d_in[5];
    const float* w_out    = (const float*)d_in[6];
    const float* b_out    = (const float*)d_in[7];
    const float* hlw      = (const float*)d_in[8];
    const float* hlb      = (const float*)d_in[9];
    const float* cgw      = (const float*)d_in[10];
    const float* cgb      = (const float*)d_in[11];
    const float* agw      = (const float*)d_in[12];
    const float* agb      = (const float*)d_in[13];
    const float* cw1      = (const float*)d_in[14];
    const float* cw2      = (const float*)d_in[15];
    const float* cw3      = (const float*)d_in[16];
    const float* aw1      = (const float*)d_in[17];
    const float* aw2      = (const float*)d_in[18];
    const float* aw3      = (const float*)d_in[19];
    const float* fw1      = (const float*)d_in[20];
    const float* fw2      = (const float*)d_in[21];
    const float* fw3      = (const float*)d_in[22];
    float* out = (float*)d_out;

    float *pq,*pk,*pv,*pca,*pcap2,*pclog,*palog,*phl,*pcm,*pam;
    float *pH1,*pH3,*pH,*pR1,*pR3,*pR,*py;
    int *pidx,*poff,*pcnt;
    cudaGetSymbolAddress((void**)&pq,    g_q);
    cudaGetSymbolAddress((void**)&pk,    g_k);
    cudaGetSymbolAddress((void**)&pv,    g_v);
    cudaGetSymbolAddress((void**)&pca,   g_ca);
    cudaGetSymbolAddress((void**)&pcap2, g_cap2);
    cudaGetSymbolAddress((void**)&pclog, g_caplog);
    cudaGetSymbolAddress((void**)&palog, g_aclog);
    cudaGetSymbolAddress((void**)&phl,   g_hl);
    cudaGetSymbolAddress((void**)&pcm,   g_cm);
    cudaGetSymbolAddress((void**)&pam,   g_am);
    cudaGetSymbolAddress((void**)&pH1,   g_H1);
    cudaGetSymbolAddress((void**)&pH3,   g_H3);
    cudaGetSymbolAddress((void**)&pH,    g_H);
    cudaGetSymbolAddress((void**)&pR1,   g_R1);
    cudaGetSymbolAddress((void**)&pR3,   g_R3);
    cudaGetSymbolAddress((void**)&pR,    g_R);
    cudaGetSymbolAddress((void**)&py,    g_y);
    cudaGetSymbolAddress((void**)&pidx,  g_idx);
    cudaGetSymbolAddress((void**)&poff,  g_off);
    cudaGetSymbolAddress((void**)&pcnt,  g_cnt);

    cudaFuncSetAttribute(attn2, cudaFuncAttributeMaxDynamicSharedMemorySize, SMEM_ATTN);
    cudaFuncSetAttribute(gemm_tc<0,0>, cudaFuncAttributeMaxDynamicSharedMemorySize, SMEM_GEMM);
    cudaFuncSetAttribute(gemm_tc<1,0>, cudaFuncAttributeMaxDynamicSharedMemorySize, SMEM_GEMM);
    cudaFuncSetAttribute(gemm_tc<1,1>, cudaFuncAttributeMaxDynamicSharedMemorySize, SMEM_GEMM);
    cudaFuncSetAttribute(gemm_tc<1,2>, cudaFuncAttributeMaxDynamicSharedMemorySize, SMEM_GEMM);

    const long long HDM = (long long)HIDN*DM;
    const long long DHI = (long long)DM*HIDN;

    // 1) Q = x @ w_in[0:D].T + b
    gemm_tc<0,0><<<dim3(18,16,1),128,SMEM_GEMM>>>(x, DM, 0, w_in, DM, 0, b_in,
        pq, DM, 0, nullptr,nullptr,nullptr,0, nullptr, NROW, DM, DM);
    // 2) K, V from caption
    gemm_tc<0,0><<<dim3(18,2,1),128,SMEM_GEMM>>>(caption, DM, 0, w_in + (long long)DM*DM, DM, 0, b_in + DM,
        pk, DM, 0, nullptr,nullptr,nullptr,0, nullptr, SKV, DM, DM);
    gemm_tc<0,0><<<dim3(18,2,1),128,SMEM_GEMM>>>(caption, DM, 0, w_in + 2LL*DM*DM, DM, 0, b_in + 2*DM,
        pv, DM, 0, nullptr,nullptr,nullptr,0, nullptr, SKV, DM, DM);
    // 3) attention
    attn2<<<dim3(16,8,2),256,SMEM_ATTN>>>(pq, pk, pv, pca);
    // 4) out proj
    gemm_tc<0,0><<<dim3(18,16,1),128,SMEM_GEMM>>>(pca, DM, 0, w_out, DM, 0, b_out,
        pcap2, DM, 0, nullptr,nullptr,nullptr,0, nullptr, NROW, DM, DM);
    // 5) hl + gate logits
    hlk<<<1,128>>>(timei, hlw, hlb, phl);
    gate4<<<NROW/8,256>>>(pcap2, cgw, cgb, pclog);
    gate4<<<NROW/8,256>>>(acoustic, agw, agb, palog);
    // 6) gating + routing
    init_counts<<<1,32>>>();
    gating_kernel<<<8,256>>>(pclog, palog);
    offsets_kernel<<<1,1>>>();
    scatter_kernel<<<8,256>>>();
    // 7) MoE cap branch
    gemm_tc<1,0><<<dim3(12,16,4),128,SMEM_GEMM>>>(x, DM, 0, cw1, DM, HDM, nullptr,
        pH1, HIDN, 0, pidx,poff,pcnt,0, nullptr, NROW, HIDN, DM);
    gemm_tc<1,0><<<dim3(12,16,4),128,SMEM_GEMM>>>(x, DM, 0, cw3, DM, HDM, nullptr,
        pH3, HIDN, 0, pidx,poff,pcnt,0, nullptr, NROW, HIDN, DM);
    silumul4<<<NROW*HIDN/4/256,256>>>((const float4*)pH1,(const float4*)pH3,(float4*)pH, NROW*HIDN/4);
    gemm_tc<1,1><<<dim3(18,16,4),128,SMEM_GEMM>>>(pH, HIDN, 0, cw2, HIDN, DHI, nullptr,
        py, DM, 0, pidx,poff,pcnt,0, pcm, NROW, DM, HIDN);
    // 8) MoE ac branch
    gemm_tc<1,0><<<dim3(12,16,4),128,SMEM_GEMM>>>(x, DM, 0, aw1, DM, HDM, nullptr,
        pH1, HIDN, 0, pidx,poff,pcnt,4, nullptr, NROW, HIDN, DM);
    gemm_tc<1,0><<<dim3(12,16,4),128,SMEM_GEMM>>>(x, DM, 0, aw3, DM, HDM, nullptr,
        pH3, HIDN, 0, pidx,poff,pcnt,4, nullptr, NROW, HIDN, DM);
    silumul4<<<NROW*HIDN/4/256,256>>>((const float4*)pH1,(const float4*)pH3,(float4*)pH, NROW*HIDN/4);
    gemm_tc<1,2><<<dim3(18,16,4),128,SMEM_GEMM>>>(pH, HIDN, 0, aw2, HIDN, DHI, nullptr,
        py, DM, 0, pidx,poff,pcnt,4, pam, NROW, DM, HIDN);
    // 9) region FF
    gemm_tc<0,0><<<dim3(12,16,4),128,SMEM_GEMM>>>(py, DM, REG, fw1, DM, HDM + REG, nullptr,
        pR1, HIDN, (long long)NROW*HIDN, nullptr,nullptr,nullptr,0, nullptr, NROW, HIDN, REG);
    gemm_tc<0,0><<<dim3(12,16,4),128,SMEM_GEMM>>>(py, DM, REG, fw3, DM, HDM + REG, nullptr,
        pR3, HIDN, (long long)NROW*HIDN, nullptr,nullptr,nullptr,0, nullptr, NROW, HIDN, REG);
    silumul4<<<4*NROW*HIDN/4/256,256>>>((const float4*)pR1,(const float4*)pR3,(float4*)pR, 4*NROW*HIDN/4);
    gemm_tc<0,0><<<dim3(5,16,4),128,SMEM_GEMM>>>(pR, HIDN, (long long)NROW*HIDN, fw2, HIDN, DHI + (long long)REG*HIDN, nullptr,
        out, DM, REG, nullptr,nullptr,nullptr,0, nullptr, NROW, REG, HIDN);
    // 10) lb loss scalar
    long long zElems = (long long)NROW * DM;
    long long i1 = ((long long)out_size > zElems) ? zElems : -1;
    lb_kernel<<<1,256>>>(out, i1);
}

// round 8
// speedup vs baseline: 1.5782x; 1.5782x over previous
#include <cuda_runtime.h>
#include <cuda_bf16.h>
#include <cstdint>

#define NROW 2048
#define DM   1152
#define SKV  256
#define HIDN 768
#define REG  288   // DM/4
#define EW   (4*HIDN*DM)   // one expert-weight tensor (4 experts)

// ---------------- scratch (device globals; allocation-free) ----------------
__device__ float g_q[NROW*DM];
__device__ float g_k[SKV*DM];
__device__ float g_v[SKV*DM];
__device__ float g_ca[NROW*DM];
__device__ float g_cap2[NROW*DM];
__device__ float g_caplog[NROW*4];
__device__ float g_aclog[NROW*4];
__device__ float g_hl[4];
__device__ float g_cm[NROW];
__device__ float g_am[NROW];
__device__ int   g_cpe[NROW];
__device__ int   g_ape[NROW];
__device__ int   g_cnt[8];
__device__ int   g_off[8];
__device__ int   g_cur[8];
__device__ int   g_idx[2*NROW];
__device__ float g_H1[NROW*HIDN];
__device__ float g_H3[NROW*HIDN];
__device__ float g_R1[4L*NROW*HIDN];
__device__ float g_R3[4L*NROW*HIDN];
__device__ float g_y[NROW*DM];

// bf16 hi/lo split operands
__device__ __nv_bfloat16 g_xh[NROW*DM],  g_xl[NROW*DM];
__device__ __nv_bfloat16 g_caph[SKV*DM], g_capl[SKV*DM];
__device__ __nv_bfloat16 g_winh[3*DM*DM],g_winl[3*DM*DM];
__device__ __nv_bfloat16 g_wouth[DM*DM], g_woutl[DM*DM];
__device__ __nv_bfloat16 g_ewh[9L*EW],   g_ewl[9L*EW];
__device__ __nv_bfloat16 g_cah[NROW*DM], g_cal[NROW*DM];
__device__ __nv_bfloat16 g_Hh[NROW*HIDN],g_Hl[NROW*HIDN];
__device__ __nv_bfloat16 g_yh[NROW*DM],  g_yl[NROW*DM];
__device__ __nv_bfloat16 g_Rh[4L*NROW*HIDN], g_Rl[4L*NROW*HIDN];

// ---------------- helpers ----------------
__device__ __forceinline__ uint32_t smem_to_u32(const void* p) {
    uint32_t a;
    asm("{ .reg .u64 t; cvta.to.shared.u64 t, %1; cvt.u32.u64 %0, t; }" : "=r"(a) : "l"(p));
    return a;
}

#define CPA(dst, src, sz) \
    asm volatile("cp.async.cg.shared.global [%0], [%1], 16, %2;" \
                 :: "r"(dst), "l"(src), "r"(sz) : "memory")
#define CPA_COMMIT() asm volatile("cp.async.commit_group;" ::: "memory")
#define CPA_WAIT0()  asm volatile("cp.async.wait_group 0;" ::: "memory")

#define LDSM4(r0, r1, r2, r3, addr) \
    asm volatile("ldmatrix.sync.aligned.m8n8.x4.shared.b16 {%0,%1,%2,%3}, [%4];" \
                 : "=r"(r0), "=r"(r1), "=r"(r2), "=r"(r3) : "r"(addr))

__device__ __forceinline__ void mma16(float* d, const uint32_t* a, const uint32_t* b)
{
    asm volatile(
        "mma.sync.aligned.m16n8k16.row.col.f32.bf16.bf16.f32 "
        "{%0,%1,%2,%3}, {%4,%5,%6,%7}, {%8,%9}, {%0,%1,%2,%3};\n"
        : "+f"(d[0]), "+f"(d[1]), "+f"(d[2]), "+f"(d[3])
        : "r"(a[0]), "r"(a[1]), "r"(a[2]), "r"(a[3]), "r"(b[0]), "r"(b[1]));
}

// ---------------- threefry2x32-20 (exact JAX, partitionable) ----------------
__device__ __forceinline__ uint32_t rotl32(uint32_t v, int r){ return (v<<r)|(v>>(32-r)); }

__device__ __forceinline__ void tf2x32(uint32_t k0, uint32_t k1, uint32_t x0, uint32_t x1,
                                       uint32_t& o0, uint32_t& o1)
{
    uint32_t ks2 = k0 ^ k1 ^ 0x1BD11BDAu;
    x0 += k0; x1 += k1;
#define TFR(r) { x0 += x1; x1 = rotl32(x1,(r)); x1 ^= x0; }
    TFR(13) TFR(15) TFR(26) TFR(6)   x0 += k1;  x1 += ks2 + 1u;
    TFR(17) TFR(29) TFR(16) TFR(24)  x0 += ks2; x1 += k0  + 2u;
    TFR(13) TFR(15) TFR(26) TFR(6)   x0 += k0;  x1 += k1  + 3u;
    TFR(17) TFR(29) TFR(16) TFR(24)  x0 += k1;  x1 += ks2 + 4u;
    TFR(13) TFR(15) TFR(26) TFR(6)   x0 += ks2; x1 += k0  + 5u;
#undef TFR
    o0 = x0; o1 = x1;
}

__device__ __forceinline__ uint32_t jax_bits_p(uint32_t k0, uint32_t k1, uint32_t i)
{
    uint32_t o0, o1;
    tf2x32(k0, k1, 0u, i, o0, o1);
    return o0 ^ o1;
}

__device__ __forceinline__ float gumbel_from_bits(uint32_t bits)
{
    uint32_t fb = (bits >> 9) | 0x3f800000u;
    float f = __uint_as_float(fb) - 1.0f;
    const float TINY = 1.17549435e-38f;
    float u = (f > 0.0f) ? f : TINY;
    return -logf(-logf(u));
}

// ---------------- fp32 -> (bf16 hi, bf16 lo) split kernels ----------------
__device__ __forceinline__ void split4(float4 f, uint2& hi, uint2& lo)
{
    __nv_bfloat162 h0 = __floats2bfloat162_rn(f.x, f.y);
    __nv_bfloat162 h1 = __floats2bfloat162_rn(f.z, f.w);
    float r0 = f.x - __bfloat162float(h0.x);
    float r1 = f.y - __bfloat162float(h0.y);
    float r2 = f.z - __bfloat162float(h1.x);
    float r3 = f.w - __bfloat162float(h1.y);
    __nv_bfloat162 l0 = __floats2bfloat162_rn(r0, r1);
    __nv_bfloat162 l1 = __floats2bfloat162_rn(r2, r3);
    hi = make_uint2(*(uint32_t*)&h0, *(uint32_t*)&h1);
    lo = make_uint2(*(uint32_t*)&l0, *(uint32_t*)&l1);
}

__global__ void cvt_split(const float4* __restrict__ src, uint2* __restrict__ hi,
                          uint2* __restrict__ lo, int n4)
{
    int i = blockIdx.x*blockDim.x + threadIdx.x;
    if (i >= n4) return;
    uint2 h, l;
    split4(src[i], h, l);
    hi[i] = h; lo[i] = l;
}

__global__ void silumul_bf(const float4* __restrict__ H1, const float4* __restrict__ H3,
                           uint2* __restrict__ hi, uint2* __restrict__ lo, int n4)
{
    int i = blockIdx.x*blockDim.x + threadIdx.x;
    if (i >= n4) return;
    float4 a = H1[i], c = H3[i], r;
    r.x = a.x/(1.f+expf(-a.x))*c.x;
    r.y = a.y/(1.f+expf(-a.y))*c.y;
    r.z = a.z/(1.f+expf(-a.z))*c.z;
    r.w = a.w/(1.f+expf(-a.w))*c.w;
    uint2 h, l;
    split4(r, h, l);
    hi[i] = h; lo[i] = l;
}

// ---------------- bf16-split warp-MMA GEMM (ldmatrix + cp.async) ------------
// C[gr][n] = sum_k A[gr][k]*W[n][k]; tiles 128x128x32, 256 threads (8 warps,
// warp tile 32m x 64n). A/W pre-split bf16 hi/lo; D += hh + hl + lh.
// smem per stage (bf16, 80B row stride): Ah 10240 | Al 10240 | Bh 10240 | Bl 10240
#define STG 40960
#define GSM_SIZE (2*STG + 512)

template<int GATHER, int EPI>
__global__ __launch_bounds__(256)
void gemm_cp(const __nv_bfloat16* __restrict__ Ah, const __nv_bfloat16* __restrict__ Al,
             int lda, long long aOff,
             const __nv_bfloat16* __restrict__ Wh, const __nv_bfloat16* __restrict__ Wl,
             int ldw, long long wOff,
             const float* __restrict__ bias,
             float* __restrict__ C, int ldc, long long cOff,
             const int* __restrict__ rowIdx, const int* __restrict__ bOffA,
             const int* __restrict__ bCnt, int bBase,
             const float* __restrict__ rowScale,
             int M, int N, int K)
{
    extern __shared__ char smc[];
    const uint32_t smb = smem_to_u32(smc);
    int* rmap = (int*)(smc + 2*STG);

    const int e = blockIdx.z;
    Ah += (long long)e * aOff; Al += (long long)e * aOff;
    Wh += (long long)e * wOff; Wl += (long long)e * wOff;
    C  += (long long)e * cOff;
    int rows = M; const int* idx = nullptr;
    if (GATHER) { rows = bCnt[bBase+e]; idx = rowIdx + bOffA[bBase+e]; }
    const int m0 = blockIdx.y * 128, n0 = blockIdx.x * 128;
    if (m0 >= rows) return;

    const int tid = threadIdx.x, warp = tid >> 5, lane = tid & 31;
    const int wm = warp & 3, wn = warp >> 2;

    if (tid < 128) {
        int r = m0 + tid;
        rmap[tid] = (r < rows) ? (GATHER ? idx[r] : r) : -1;
    }
    __syncthreads();

    // loaders: thread owns row tid>>1, 32B segment (tid&1)
    const int lrow = tid >> 1;
    const int seg  = tid & 1;
    const int gr0 = rmap[lrow];
    const __nv_bfloat16* aSrcH = Ah + (gr0 >= 0 ? (long long)gr0 * lda : 0) + seg*16;
    const __nv_bfloat16* aSrcL = Al + (gr0 >= 0 ? (long long)gr0 * lda : 0) + seg*16;
    const uint32_t aSz = (gr0 >= 0) ? 16u : 0u;
    const bool nok = (n0 + lrow) < N;
    const __nv_bfloat16* bSrcH = Wh + (nok ? (long long)(n0 + lrow) * ldw : 0) + seg*16;
    const __nv_bfloat16* bSrcL = Wl + (nok ? (long long)(n0 + lrow) * ldw : 0) + seg*16;
    const uint32_t bSz = nok ? 16u : 0u;
    const uint32_t dRow = (uint32_t)lrow*80 + seg*32;

#define LOADS(c) { \
    const int k0 = (c)*32; \
    const uint32_t sb = smb + ((c)&1)*STG; \
    CPA(sb + dRow,              aSrcH + k0,     aSz); \
    CPA(sb + dRow + 16,         aSrcH + k0 + 8, aSz); \
    CPA(sb + 10240 + dRow,      aSrcL + k0,     aSz); \
    CPA(sb + 10240 + dRow + 16, aSrcL + k0 + 8, aSz); \
    CPA(sb + 20480 + dRow,      bSrcH + k0,     bSz); \
    CPA(sb + 20480 + dRow + 16, bSrcH + k0 + 8, bSz); \
    CPA(sb + 30720 + dRow,      bSrcL + k0,     bSz); \
    CPA(sb + 30720 + dRow + 16, bSrcL + k0 + 8, bSz); \
    CPA_COMMIT(); }

    // ldmatrix per-lane offsets
    const uint32_t aoff = (uint32_t)(lane & 15)*80 + (((uint32_t)lane >> 4) << 4);
    const uint32_t boff = (uint32_t)((lane & 7) + ((lane >> 4) << 3))*80 + (uint32_t)(((lane >> 3) & 1) << 4);

    float d[2][8][4];
    #pragma unroll
    for (int i = 0; i < 2; i++)
        #pragma unroll
        for (int j = 0; j < 8; j++)
            #pragma unroll
            for (int r = 0; r < 4; r++) d[i][j][r] = 0.f;

#define COMPUTES(buf) { \
    const uint32_t sb = smb + (buf)*STG; \
    _Pragma("unroll") \
    for (int ks = 0; ks < 2; ks++) { \
        uint32_t ah[2][4], al[2][4], bh[4][4], bl[4][4]; \
        _Pragma("unroll") \
        for (int mt = 0; mt < 2; mt++) { \
            uint32_t ad = sb + (uint32_t)(wm*32 + mt*16)*80 + ks*32 + aoff; \
            LDSM4(ah[mt][0], ah[mt][1], ah[mt][2], ah[mt][3], ad); \
            LDSM4(al[mt][0], al[mt][1], al[mt][2], al[mt][3], ad + 10240); \
        } \
        _Pragma("unroll") \
        for (int ng = 0; ng < 4; ng++) { \
            uint32_t bd = sb + 20480 + (uint32_t)(wn*64 + ng*16)*80 + ks*32 + boff; \
            LDSM4(bh[ng][0], bh[ng][1], bh[ng][2], bh[ng][3], bd); \
            LDSM4(bl[ng][0], bl[ng][1], bl[ng][2], bl[ng][3], bd + 10240); \
        } \
        _Pragma("unroll") \
        for (int mt = 0; mt < 2; mt++) \
            _Pragma("unroll") \
            for (int ng = 0; ng < 4; ng++) \
                _Pragma("unroll") \
                for (int h = 0; h < 2; h++) { \
                    float* dd = d[mt][ng*2 + h]; \
                    mma16(dd, ah[mt], &bh[ng][2*h]); \
                    mma16(dd, ah[mt], &bl[ng][2*h]); \
                    mma16(dd, al[mt], &bh[ng][2*h]); \
                } \
    } }

    const int nc = K / 32;
    LOADS(0)
    for (int c = 0; c < nc; c++) {
        CPA_WAIT0();
        __syncthreads();
        if (c + 1 < nc) LOADS(c+1)
        COMPUTES(c & 1)
    }
#undef LOADS
#undef COMPUTES

    // epilogue
    #pragma unroll
    for (int mt = 0; mt < 2; mt++) {
        #pragma unroll
        for (int h = 0; h < 2; h++) {
            int r = wm*32 + mt*16 + (lane >> 2) + 8*h;
            int gr = rmap[r];
            if (gr < 0) continue;
            float* crow = C + (long long)gr * ldc;
            float sc = (EPI >= 1) ? rowScale[gr] : 0.f;
            #pragma unroll
            for (int n8 = 0; n8 < 8; n8++) {
                int c0 = n0 + wn*64 + n8*8 + (lane & 3)*2;
                if (c0 >= N) continue;
                float v0 = d[mt][n8][2*h + 0];
                float v1 = d[mt][n8][2*h + 1];
                if (EPI == 0) {
                    if (bias) { v0 += bias[c0]; v1 += bias[c0+1]; }
                    *(float2*)(crow + c0) = make_float2(v0, v1);
                } else if (EPI == 1) {
                    *(float2*)(crow + c0) = make_float2(v0*sc, v1*sc);
                } else {
                    float2 o = *(float2*)(crow + c0);
                    *(float2*)(crow + c0) = make_float2(o.x + v0*sc, o.y + v1*sc);
                }
            }
        }
    }
}

// ---------------- attention: 64 queries x (head,batch) per block ------------
#define SMEM_ATTN 220160

__global__ __launch_bounds__(256)
void attn2(const float* __restrict__ Q, const float* __restrict__ K,
           const float* __restrict__ V, float* __restrict__ O)
{
    extern __shared__ float smatt[];
    float* Qs = smatt;
    float* Ks = smatt + 144*64;
    float* Vs = smatt + 144*64 + 144*128;
    float* Ss = Vs + 128*148;

    const int tid = threadIdx.x;
    const int q0 = blockIdx.x * 64;
    const int h = blockIdx.y, b = blockIdx.z;
    const long long qrow0 = (long long)b*1024 + q0;
    const int hc = h*144;

    for (int i = tid; i < 64*36; i += 256) {
        int q = i / 36, f = i % 36;
        float4 v4 = *(const float4*)(Q + (qrow0 + q)*DM + hc + f*4);
        Qs[(f*4+0)*64+q]=v4.x; Qs[(f*4+1)*64+q]=v4.y;
        Qs[(f*4+2)*64+q]=v4.z; Qs[(f*4+3)*64+q]=v4.w;
    }
    for (int i = tid; i < 128*36; i += 256) {
        int k = i / 36, f = i % 36;
        float4 v4 = *(const float4*)(K + ((long long)b*128 + k)*DM + hc + f*4);
        Ks[(f*4+0)*128+k]=v4.x; Ks[(f*4+1)*128+k]=v4.y;
        Ks[(f*4+2)*128+k]=v4.z; Ks[(f*4+3)*128+k]=v4.w;
        float4 w4 = *(const float4*)(V + ((long long)b*128 + k)*DM + hc + f*4);
        *(float4*)&Vs[k*148 + f*4] = w4;
    }
    __syncthreads();

    const int tx = tid & 15, ty = tid >> 4;

    {
        float acc[4][8] = {};
        for (int d = 0; d < 144; d++) {
            float a[4], bv[8];
            *(float4*)a      = *(const float4*)&Qs[d*64 + ty*4];
            *(float4*)bv     = *(const float4*)&Ks[d*128 + tx*8];
            *(float4*)(bv+4) = *(const float4*)&Ks[d*128 + tx*8 + 4];
            #pragma unroll
            for (int i = 0; i < 4; i++)
                #pragma unroll
                for (int j = 0; j < 8; j++) acc[i][j] += a[i]*bv[j];
        }
        #pragma unroll
        for (int i = 0; i < 4; i++)
            #pragma unroll
            for (int j = 0; j < 8; j++)
                Ss[(ty*4+i)*132 + tx*8 + j] = acc[i][j] * (1.0f/12.0f);
    }
    __syncthreads();

    if (tid < 64) {
        float* r = Ss + tid*132;
        float mx = -1e30f;
        for (int k = 0; k < 128; k++) mx = fmaxf(mx, r[k]);
        float sum = 0.f;
        for (int k = 0; k < 128; k++) { float ev = expf(r[k]-mx); r[k] = ev; sum += ev; }
        float inv = 1.0f / sum;
        for (int k = 0; k < 128; k++) r[k] *= inv;
    }
    __syncthreads();

    {
        float o[4][9] = {};
        for (int k = 0; k < 128; k++) {
            float s[4];
            #pragma unroll
            for (int i = 0; i < 4; i++) s[i] = Ss[(ty*4+i)*132 + k];
            #pragma unroll
            for (int j = 0; j < 9; j++) {
                float vv = Vs[k*148 + tx*9 + j];
                #pragma unroll
                for (int i = 0; i < 4; i++) o[i][j] += s[i]*vv;
            }
        }
        #pragma unroll
        for (int i = 0; i < 4; i++)
            #pragma unroll
            for (int j = 0; j < 9; j++)
                O[(qrow0 + ty*4 + i)*DM + hc + tx*9 + j] = o[i][j];
    }
}

// ---------------- small exact kernels ----------------
__global__ void gate4(const float* __restrict__ A, const float* __restrict__ W,
                      const float* __restrict__ b, float* __restrict__ out)
{
    int w = blockIdx.x*8 + (threadIdx.x >> 5);
    int lane = threadIdx.x & 31;
    if (w >= NROW) return;
    const float* a = A + (long long)w*DM;
    float s0=0,s1=0,s2=0,s3=0;
    for (int c = lane*4; c < DM; c += 128) {
        float4 av = *(const float4*)(a + c);
        float4 w0 = *(const float4*)(W + c);
        float4 w1 = *(const float4*)(W + DM + c);
        float4 w2 = *(const float4*)(W + 2*DM + c);
        float4 w3 = *(const float4*)(W + 3*DM + c);
        s0 += av.x*w0.x + av.y*w0.y + av.z*w0.z + av.w*w0.w;
        s1 += av.x*w1.x + av.y*w1.y + av.z*w1.z + av.w*w1.w;
        s2 += av.x*w2.x + av.y*w2.y + av.z*w2.z + av.w*w2.w;
        s3 += av.x*w3.x + av.y*w3.y + av.z*w3.z + av.w*w3.w;
    }
    #pragma unroll
    for (int o = 16; o > 0; o >>= 1) {
        s0 += __shfl_xor_sync(0xffffffffu, s0, o);
        s1 += __shfl_xor_sync(0xffffffffu, s1, o);
        s2 += __shfl_xor_sync(0xffffffffu, s2, o);
        s3 += __shfl_xor_sync(0xffffffffu, s3, o);
    }
    if (lane == 0) {
        out[w*4+0] = s0 + b[0]; out[w*4+1] = s1 + b[1];
        out[w*4+2] = s2 + b[2]; out[w*4+3] = s3 + b[3];
    }
}

__global__ void hlk(const float* __restrict__ t, const float* __restrict__ w,
                    const float* __restrict__ bb, float* __restrict__ hl)
{
    int wi = threadIdx.x >> 5, lane = threadIdx.x & 31;
    int r = wi >> 1, o = wi & 1;
    const float* a = t + r*DM;
    const float* ww = w + o*DM;
    float s = 0.f;
    for (int c = lane*4; c < DM; c += 128) {
        float4 av = *(const float4*)(a + c);
        float4 wv = *(const float4*)(ww + c);
        s += av.x*wv.x + av.y*wv.y + av.z*wv.z + av.w*wv.w;
    }
    #pragma unroll
    for (int off = 16; off > 0; off >>= 1) s += __shfl_xor_sync(0xffffffffu, s, off);
    if (lane == 0) hl[r*2+o] = s + bb[o];
}

// ---------------- gating + routing ----------------
__global__ void init_counts()
{
    if (threadIdx.x < 8) g_cnt[threadIdx.x] = 0;
}

__global__ void gating_kernel(const float* __restrict__ caplog, const float* __restrict__ aclog)
{
    int n = blockIdx.x * blockDim.x + threadIdx.x;
    if (n >= NROW) return;

    uint32_t k1a,k1b,k2a,k2b,k3a,k3b;
    tf2x32(0u, 42u, 0u, 0u, k1a, k1b);
    tf2x32(0u, 42u, 0u, 1u, k2a, k2b);
    tf2x32(0u, 42u, 0u, 2u, k3a, k3b);

    float g0 = gumbel_from_bits(jax_bits_p(k1a, k1b, 2u*(uint32_t)n + 0u));
    float g1 = gumbel_from_bits(jax_bits_p(k1a, k1b, 2u*(uint32_t)n + 1u));
    int bb = n >> 10;
    float l0 = g_hl[2*bb + 0] + g0;
    float l1 = g_hl[2*bb + 1] + g1;
    float mx = fmaxf(l0, l1);
    float e0 = expf(l0 - mx), e1 = expf(l1 - mx);
    float inv = 1.0f / (e0 + e1);
    g_cm[n] = e0 * inv;
    g_am[n] = e1 * inv;

    int be = 0; float bv = -1e30f;
    #pragma unroll
    for (int c = 0; c < 4; c++) {
        float g = gumbel_from_bits(jax_bits_p(k2a, k2b, 4u*(uint32_t)n + (uint32_t)c));
        float yv = caplog[n*4 + c] + g;
        if (yv > bv) { bv = yv; be = c; }
    }
    g_cpe[n] = be;
    atomicAdd(&g_cnt[be], 1);

    int ae = 0; bv = -1e30f;
    #pragma unroll
    for (int c = 0; c < 4; c++) {
        float g = gumbel_from_bits(jax_bits_p(k3a, k3b, 4u*(uint32_t)n + (uint32_t)c));
        float yv = aclog[n*4 + c] + g;
        if (yv > bv) { bv = yv; ae = c; }
    }
    g_ape[n] = ae;
    atomicAdd(&g_cnt[4 + ae], 1);
}

__global__ void offsets_kernel()
{
    int o = 0;
    for (int e = 0; e < 4; e++) { g_off[e] = o; o += g_cnt[e]; }
    o = NROW;
    for (int e = 4; e < 8; e++) { g_off[e] = o; o += g_cnt[e]; }
    for (int j = 0; j < 8; j++) g_cur[j] = g_off[j];
}

__global__ void scatter_kernel()
{
    int n = blockIdx.x * blockDim.x + threadIdx.x;
    if (n >= NROW) return;
    int e = g_cpe[n];
    int p = atomicAdd(&g_cur[e], 1);
    g_idx[p] = n;
    int a = g_ape[n];
    p = atomicAdd(&g_cur[4 + a], 1);
    g_idx[p] = n;
}

// ---------------- lb loss ----------------
__global__ void lb_kernel(float* __restrict__ outp, long long i1)
{
    __shared__ float sh[256 * 9];
    int t = threadIdx.x;
    float u[8] = {0,0,0,0,0,0,0,0};
    float ms = 0.f;
    for (int n = t; n < NROW; n += 256) {
        u[g_cpe[n]]     += g_cm[n];
        u[4 + g_ape[n]] += g_am[n];
        ms += g_cm[n] + g_am[n];
    }
    #pragma unroll
    for (int j = 0; j < 8; j++) sh[t*9 + j] = u[j];
    sh[t*9 + 8] = ms;
    __syncthreads();
    for (int stride = 128; stride > 0; stride >>= 1) {
        if (t < stride)
            #pragma unroll
            for (int j = 0; j < 9; j++) sh[t*9 + j] += sh[(t + stride)*9 + j];
        __syncthreads();
    }
    if (t == 0 && i1 >= 0) {
        float denom = 4.0f * sh[8] + 1e-10f;
        float acc = 0.f;
        for (int j = 0; j < 8; j++) {
            float uu = sh[j] / denom;
            acc += uu * logf(uu + 1e-10f);
        }
        outp[i1] = acc / 8.0f;
    }
}

// ---------------- host launcher ----------------
static inline void cvt(const float* src, __nv_bfloat16* h, __nv_bfloat16* l, long long n)
{
    int n4 = (int)(n / 4);
    cvt_split<<<(n4 + 255)/256, 256>>>((const float4*)src, (uint2*)h, (uint2*)l, n4);
}

extern "C" void kernel_launch(void* const* d_in, const int* in_sizes, int n_in,
                              void* d_out, int out_size)
{
    const float* x        = (const float*)d_in[0];
    const float* timei    = (const float*)d_in[1];
    const float* caption  = (const float*)d_in[2];
    const float* acoustic = (const float*)d_in[3];
    const float* w_in     = (const float*)d_in[4];
    const float* b_in     = (const float*)d_in[5];
    const float* w_out    = (const float*)d_in[6];
    const float* b_out    = (const float*)d_in[7];
    const float* hlw      = (const float*)d_in[8];
    const float* hlb      = (const float*)d_in[9];
    const float* cgw      = (const float*)d_in[10];
    const float* cgb      = (const float*)d_in[11];
    const float* agw      = (const float*)d_in[12];
    const float* agb      = (const float*)d_in[13];
    const float* ew[9] = { (const float*)d_in[14], (const float*)d_in[15], (const float*)d_in[16],
                           (const float*)d_in[17], (const float*)d_in[18], (const float*)d_in[19],
                           (const float*)d_in[20], (const float*)d_in[21], (const float*)d_in[22] };
    float* out = (float*)d_out;

    float *pq,*pk,*pv,*pca,*pcap2,*pclog,*palog,*phl,*pcm,*pam,*pH1,*pH3,*pR1,*pR3,*py;
    int *pidx,*poff,*pcnt;
    __nv_bfloat16 *xh,*xl,*cph,*cpl,*winh,*winl,*wouth,*woutl,*ewh,*ewl,*cah,*cal,*Hh,*Hl,*yh,*yl,*Rh,*Rl;

    cudaGetSymbolAddress((void**)&pq,    g_q);
    cudaGetSymbolAddress((void**)&pk,    g_k);
    cudaGetSymbolAddress((void**)&pv,    g_v);
    cudaGetSymbolAddress((void**)&pca,   g_ca);
    cudaGetSymbolAddress((void**)&pcap2, g_cap2);
    cudaGetSymbolAddress((void**)&pclog, g_caplog);
    cudaGetSymbolAddress((void**)&palog, g_aclog);
    cudaGetSymbolAddress((void**)&phl,   g_hl);
    cudaGetSymbolAddress((void**)&pcm,   g_cm);
    cudaGetSymbolAddress((void**)&pam,   g_am);
    cudaGetSymbolAddress((void**)&pH1,   g_H1);
    cudaGetSymbolAddress((void**)&pH3,   g_H3);
    cudaGetSymbolAddress((void**)&pR1,   g_R1);
    cudaGetSymbolAddress((void**)&pR3,   g_R3);
    cudaGetSymbolAddress((void**)&py,    g_y);
    cudaGetSymbolAddress((void**)&pidx,  g_idx);
    cudaGetSymbolAddress((void**)&poff,  g_off);
    cudaGetSymbolAddress((void**)&pcnt,  g_cnt);
    cudaGetSymbolAddress((void**)&xh,    g_xh);
    cudaGetSymbolAddress((void**)&xl,    g_xl);
    cudaGetSymbolAddress((void**)&cph,   g_caph);
    cudaGetSymbolAddress((void**)&cpl,   g_capl);
    cudaGetSymbolAddress((void**)&winh,  g_winh);
    cudaGetSymbolAddress((void**)&winl,  g_winl);
    cudaGetSymbolAddress((void**)&wouth, g_wouth);
    cudaGetSymbolAddress((void**)&woutl, g_woutl);
    cudaGetSymbolAddress((void**)&ewh,   g_ewh);
    cudaGetSymbolAddress((void**)&ewl,   g_ewl);
    cudaGetSymbolAddress((void**)&cah,   g_cah);
    cudaGetSymbolAddress((void**)&cal,   g_cal);
    cudaGetSymbolAddress((void**)&Hh,    g_Hh);
    cudaGetSymbolAddress((void**)&Hl,    g_Hl);
    cudaGetSymbolAddress((void**)&yh,    g_yh);
    cudaGetSymbolAddress((void**)&yl,    g_yl);
    cudaGetSymbolAddress((void**)&Rh,    g_Rh);
    cudaGetSymbolAddress((void**)&Rl,    g_Rl);

    cudaFuncSetAttribute(attn2, cudaFuncAttributeMaxDynamicSharedMemorySize, SMEM_ATTN);
    cudaFuncSetAttribute(gemm_cp<0,0>, cudaFuncAttributeMaxDynamicSharedMemorySize, GSM_SIZE);
    cudaFuncSetAttribute(gemm_cp<1,0>, cudaFuncAttributeMaxDynamicSharedMemorySize, GSM_SIZE);
    cudaFuncSetAttribute(gemm_cp<1,1>, cudaFuncAttributeMaxDynamicSharedMemorySize, GSM_SIZE);
    cudaFuncSetAttribute(gemm_cp<1,2>, cudaFuncAttributeMaxDynamicSharedMemorySize, GSM_SIZE);

    const long long HDM = (long long)HIDN*DM;
    const long long DHI = (long long)DM*HIDN;

    // 0) split conversions for static operands
    cvt(x,       xh,   xl,   (long long)NROW*DM);
    cvt(caption, cph,  cpl,  (long long)SKV*DM);
    cvt(w_in,    winh, winl, 3LL*DM*DM);
    cvt(w_out,   wouth,woutl,(long long)DM*DM);
    for (int m = 0; m < 9; m++)
        cvt(ew[m], ewh + (long long)m*EW, ewl + (long long)m*EW, (long long)EW);

    // 1) Q/K/V projections
    gemm_cp<0,0><<<dim3(9,16,1),256,GSM_SIZE>>>(xh, xl, DM, 0, winh, winl, DM, 0, b_in,
        pq, DM, 0, nullptr,nullptr,nullptr,0, nullptr, NROW, DM, DM);
    gemm_cp<0,0><<<dim3(9,2,1),256,GSM_SIZE>>>(cph, cpl, DM, 0, winh + (long long)DM*DM, winl + (long long)DM*DM, DM, 0, b_in + DM,
        pk, DM, 0, nullptr,nullptr,nullptr,0, nullptr, SKV, DM, DM);
    gemm_cp<0,0><<<dim3(9,2,1),256,GSM_SIZE>>>(cph, cpl, DM, 0, winh + 2LL*DM*DM, winl + 2LL*DM*DM, DM, 0, b_in + 2*DM,
        pv, DM, 0, nullptr,nullptr,nullptr,0, nullptr, SKV, DM, DM);
    // 2) attention
    attn2<<<dim3(16,8,2),256,SMEM_ATTN>>>(pq, pk, pv, pca);
    // 3) out proj
    cvt(pca, cah, cal, (long long)NROW*DM);
    gemm_cp<0,0><<<dim3(9,16,1),256,GSM_SIZE>>>(cah, cal, DM, 0, wouth, woutl, DM, 0, b_out,
        pcap2, DM, 0, nullptr,nullptr,nullptr,0, nullptr, NROW, DM, DM);
    // 4) hl + gate logits (exact fp32)
    hlk<<<1,128>>>(timei, hlw, hlb, phl);
    gate4<<<NROW/8,256>>>(pcap2, cgw, cgb, pclog);
    gate4<<<NROW/8,256>>>(acoustic, agw, agb, palog);
    // 5) gating + routing
    init_counts<<<1,32>>>();
    gating_kernel<<<8,256>>>(pclog, palog);
    offsets_kernel<<<1,1>>>();
    scatter_kernel<<<8,256>>>();
    // 6) MoE cap branch
    gemm_cp<1,0><<<dim3(6,16,4),256,GSM_SIZE>>>(xh, xl, DM, 0, ewh + 0LL*EW, ewl + 0LL*EW, DM, HDM, nullptr,
        pH1, HIDN, 0, pidx,poff,pcnt,0, nullptr, NROW, HIDN, DM);
    gemm_cp<1,0><<<dim3(6,16,4),256,GSM_SIZE>>>(xh, xl, DM, 0, ewh + 2LL*EW, ewl + 2LL*EW, DM, HDM, nullptr,
        pH3, HIDN, 0, pidx,poff,pcnt,0, nullptr, NROW, HIDN, DM);
    silumul_bf<<<NROW*HIDN/4/256,256>>>((const float4*)pH1,(const float4*)pH3,(uint2*)Hh,(uint2*)Hl, NROW*HIDN/4);
    gemm_cp<1,1><<<dim3(9,16,4),256,GSM_SIZE>>>(Hh, Hl, HIDN, 0, ewh + 1LL*EW, ewl + 1LL*EW, HIDN, DHI, nullptr,
        py, DM, 0, pidx,poff,pcnt,0, pcm, NROW, DM, HIDN);
    // 7) MoE ac branch
    gemm_cp<1,0><<<dim3(6,16,4),256,GSM_SIZE>>>(xh, xl, DM, 0, ewh + 3LL*EW, ewl + 3LL*EW, DM, HDM, nullptr,
        pH1, HIDN, 0, pidx,poff,pcnt,4, nullptr, NROW, HIDN, DM);
    gemm_cp<1,0><<<dim3(6,16,4),256,GSM_SIZE>>>(xh, xl, DM, 0, ewh + 5LL*EW, ewl + 5LL*EW, DM, HDM, nullptr,
        pH3, HIDN, 0, pidx,poff,pcnt,4, nullptr, NROW, HIDN, DM);
    silumul_bf<<<NROW*HIDN/4/256,256>>>((const float4*)pH1,(const float4*)pH3,(uint2*)Hh,(uint2*)Hl, NROW*HIDN/4);
    gemm_cp<1,2><<<dim3(9,16,4),256,GSM_SIZE>>>(Hh, Hl, HIDN, 0, ewh + 4LL*EW, ewl + 4LL*EW, HIDN, DHI, nullptr,
        py, DM, 0, pidx,poff,pcnt,4, pam, NROW, DM, HIDN);
    // 8) region FF
    cvt(py, yh, yl, (long long)NROW*DM);
    gemm_cp<0,0><<<dim3(6,16,4),256,GSM_SIZE>>>(yh, yl, DM, REG, ewh + 6LL*EW, ewl + 6LL*EW, DM, HDM + REG, nullptr,
        pR1, HIDN, (long long)NROW*HIDN, nullptr,nullptr,nullptr,0, nullptr, NROW, HIDN, REG);
    gemm_cp<0,0><<<dim3(6,16,4),256,GSM_SIZE>>>(yh, yl, DM, REG, ewh + 8LL*EW, ewl + 8LL*EW, DM, HDM + REG, nullptr,
        pR3, HIDN, (long long)NROW*HIDN, nullptr,nullptr,nullptr,0, nullptr, NROW, HIDN, REG);
    silumul_bf<<<4*NROW*HIDN/4/256,256>>>((const float4*)pR1,(const float4*)pR3,(uint2*)Rh,(uint2*)Rl, 4*NROW*HIDN/4);
    gemm_cp<0,0><<<dim3(3,16,4),256,GSM_SIZE>>>(Rh, Rl, HIDN, (long long)NROW*HIDN, ewh + 7LL*EW, ewl + 7LL*EW, HIDN, DHI + (long long)REG*HIDN, nullptr,
        out, DM, REG, nullptr,nullptr,nullptr,0, nullptr, NROW, REG, HIDN);
    // 9) lb loss scalar
    long long zElems = (long long)NROW * DM;
    long long i1 = ((long long)out_size > zElems) ? zElems : -1;
    lb_kernel<<<1,256>>>(out, i1);
}

// round 9
// speedup vs baseline: 1.6801x; 1.0646x over previous
#include <cuda_runtime.h>
#include <cuda_bf16.h>
#include <cstdint>

#define NROW 2048
#define DM   1152
#define SKV  256
#define HIDN 768
#define REG  288            // DM/4
#define HDM  (HIDN*DM)      // one expert matrix (either orientation)

// ---------------- scratch (device globals; allocation-free) ----------------
__device__ float g_q[NROW*DM];
__device__ float g_k[SKV*DM];
__device__ float g_v[SKV*DM];
__device__ float g_ca[NROW*DM];
__device__ float g_cap2[NROW*DM];
__device__ float g_caplog[NROW*4];
__device__ float g_aclog[NROW*4];
__device__ float g_hl[4];
__device__ float g_cm[NROW];
__device__ float g_am[NROW];
__device__ int   g_cpe[NROW];
__device__ int   g_ape[NROW];
__device__ int   g_cnt[8];
__device__ int   g_off[8];
__device__ int   g_cur[8];
__device__ int   g_idx[2*NROW];          // perm position -> original row
__device__ float g_H[4096L*1536];        // MoE up combined (h1|h3), perm order
__device__ float g_R[8192L*1536];        // region up combined
__device__ float g_y[NROW*DM];

// bf16 hi/lo split operands
__device__ __nv_bfloat16 g_xh[NROW*DM],  g_xl[NROW*DM];
__device__ __nv_bfloat16 g_gxh[2*NROW*DM], g_gxl[2*NROW*DM];   // permuted x (4096 rows)
__device__ __nv_bfloat16 g_caph[SKV*DM], g_capl[SKV*DM];
__device__ __nv_bfloat16 g_winh[3*DM*DM],g_winl[3*DM*DM];
__device__ __nv_bfloat16 g_wouth[DM*DM], g_woutl[DM*DM];
__device__ __nv_bfloat16 g_ewh[36L*HDM], g_ewl[36L*HDM];       // slotted expert weights
__device__ __nv_bfloat16 g_cah[NROW*DM], g_cal[NROW*DM];
__device__ __nv_bfloat16 g_Hh[4096L*HIDN], g_Hl[4096L*HIDN];
__device__ __nv_bfloat16 g_yh[NROW*DM],  g_yl[NROW*DM];
__device__ __nv_bfloat16 g_Rh[8192L*HIDN], g_Rl[8192L*HIDN];

// ---------------- helpers ----------------
__device__ __forceinline__ uint32_t smem_to_u32(const void* p) {
    uint32_t a;
    asm("{ .reg .u64 t; cvta.to.shared.u64 t, %1; cvt.u32.u64 %0, t; }" : "=r"(a) : "l"(p));
    return a;
}

#define CPA(dst, src, sz) \
    asm volatile("cp.async.cg.shared.global [%0], [%1], 16, %2;" \
                 :: "r"(dst), "l"(src), "r"(sz) : "memory")
#define CPA_COMMIT() asm volatile("cp.async.commit_group;" ::: "memory")
#define CPA_WAIT0()  asm volatile("cp.async.wait_group 0;" ::: "memory")

#define LDSM4(r0, r1, r2, r3, addr) \
    asm volatile("ldmatrix.sync.aligned.m8n8.x4.shared.b16 {%0,%1,%2,%3}, [%4];" \
                 : "=r"(r0), "=r"(r1), "=r"(r2), "=r"(r3) : "r"(addr))

__device__ __forceinline__ void mma16(float* d, const uint32_t* a, const uint32_t* b)
{
    asm volatile(
        "mma.sync.aligned.m16n8k16.row.col.f32.bf16.bf16.f32 "
        "{%0,%1,%2,%3}, {%4,%5,%6,%7}, {%8,%9}, {%0,%1,%2,%3};\n"
        : "+f"(d[0]), "+f"(d[1]), "+f"(d[2]), "+f"(d[3])
        : "r"(a[0]), "r"(a[1]), "r"(a[2]), "r"(a[3]), "r"(b[0]), "r"(b[1]));
}

// ---------------- threefry2x32-20 (exact JAX, partitionable) ----------------
__device__ __forceinline__ uint32_t rotl32(uint32_t v, int r){ return (v<<r)|(v>>(32-r)); }

__device__ __forceinline__ void tf2x32(uint32_t k0, uint32_t k1, uint32_t x0, uint32_t x1,
                                       uint32_t& o0, uint32_t& o1)
{
    uint32_t ks2 = k0 ^ k1 ^ 0x1BD11BDAu;
    x0 += k0; x1 += k1;
#define TFR(r) { x0 += x1; x1 = rotl32(x1,(r)); x1 ^= x0; }
    TFR(13) TFR(15) TFR(26) TFR(6)   x0 += k1;  x1 += ks2 + 1u;
    TFR(17) TFR(29) TFR(16) TFR(24)  x0 += ks2; x1 += k0  + 2u;
    TFR(13) TFR(15) TFR(26) TFR(6)   x0 += k0;  x1 += k1  + 3u;
    TFR(17) TFR(29) TFR(16) TFR(24)  x0 += k1;  x1 += ks2 + 4u;
    TFR(13) TFR(15) TFR(26) TFR(6)   x0 += ks2; x1 += k0  + 5u;
#undef TFR
    o0 = x0; o1 = x1;
}

__device__ __forceinline__ uint32_t jax_bits_p(uint32_t k0, uint32_t k1, uint32_t i)
{
    uint32_t o0, o1;
    tf2x32(k0, k1, 0u, i, o0, o1);
    return o0 ^ o1;
}

__device__ __forceinline__ float gumbel_from_bits(uint32_t bits)
{
    uint32_t fb = (bits >> 9) | 0x3f800000u;
    float f = __uint_as_float(fb) - 1.0f;
    const float TINY = 1.17549435e-38f;
    float u = (f > 0.0f) ? f : TINY;
    return -logf(-logf(u));
}

// ---------------- fp32 -> (bf16 hi, bf16 lo) split kernels ----------------
__device__ __forceinline__ void split4(float4 f, uint2& hi, uint2& lo)
{
    __nv_bfloat162 h0 = __floats2bfloat162_rn(f.x, f.y);
    __nv_bfloat162 h1 = __floats2bfloat162_rn(f.z, f.w);
    float r0 = f.x - __bfloat162float(h0.x);
    float r1 = f.y - __bfloat162float(h0.y);
    float r2 = f.z - __bfloat162float(h1.x);
    float r3 = f.w - __bfloat162float(h1.y);
    __nv_bfloat162 l0 = __floats2bfloat162_rn(r0, r1);
    __nv_bfloat162 l1 = __floats2bfloat162_rn(r2, r3);
    hi = make_uint2(*(uint32_t*)&h0, *(uint32_t*)&h1);
    lo = make_uint2(*(uint32_t*)&l0, *(uint32_t*)&l1);
}

__global__ void cvt_split(const float4* __restrict__ src, uint2* __restrict__ hi,
                          uint2* __restrict__ lo, int n4)
{
    int i = blockIdx.x*blockDim.x + threadIdx.x;
    if (i >= n4) return;
    uint2 h, l;
    split4(src[i], h, l);
    hi[i] = h; lo[i] = l;
}

// convert w1/w3 expert pair into interleaved slots: dst slot 2e <- s1[e], 2e+1 <- s2[e]
__global__ void cvt_pair(const float4* __restrict__ s1, const float4* __restrict__ s2,
                         uint2* __restrict__ hi, uint2* __restrict__ lo, int n4per)
{
    int e = blockIdx.z;
    int i = blockIdx.x*blockDim.x + threadIdx.x;
    if (i >= n4per) return;
    uint2 h, l;
    split4(s1[(long long)e*n4per + i], h, l);
    hi[(long long)(2*e)*n4per + i] = h;
    lo[(long long)(2*e)*n4per + i] = l;
    split4(s2[(long long)e*n4per + i], h, l);
    hi[(long long)(2*e+1)*n4per + i] = h;
    lo[(long long)(2*e+1)*n4per + i] = l;
}

// silu(h1)*h3 from combined [rows][1536] (h1|h3) -> split bf16 [rows][768]
__global__ void silumul_pair(const float4* __restrict__ H, uint2* __restrict__ hi,
                             uint2* __restrict__ lo, int total)  // total = rows*192
{
    int i = blockIdx.x*blockDim.x + threadIdx.x;
    if (i >= total) return;
    int row = i / 192, j = i % 192;
    float4 a = H[(long long)row*384 + j];
    float4 c = H[(long long)row*384 + 192 + j];
    float4 r;
    r.x = a.x/(1.f+expf(-a.x))*c.x;
    r.y = a.y/(1.f+expf(-a.y))*c.y;
    r.z = a.z/(1.f+expf(-a.z))*c.z;
    r.w = a.w/(1.f+expf(-a.w))*c.w;
    uint2 h, l;
    split4(r, h, l);
    hi[i] = h; lo[i] = l;
}

// gather x rows into permuted (bucket-contiguous) order
__global__ void permute_x(const uint4* __restrict__ xh, const uint4* __restrict__ xl,
                          uint4* __restrict__ gh, uint4* __restrict__ gl)
{
    const int W16 = DM/8;   // 144 uint4 per row
    int p = blockIdx.x;
    int src = g_idx[p];
    for (int c = threadIdx.x; c < W16; c += blockDim.x) {
        gh[(long long)p*W16 + c] = xh[(long long)src*W16 + c];
        gl[(long long)p*W16 + c] = xl[(long long)src*W16 + c];
    }
}

// ---------------- bf16-split warp-MMA GEMM (ldmatrix + cp.async) ------------
// C[cr][n] = sum_k A[ar][k]*W[n][k]; tiles 128x128x32, 256 threads, 8 warps
// (warp tile 32m x 64n). 3-term: D += hh + hl + lh.
// AMODE 0: rows=M, ar = m0+r (A pre-shifted by e*aOff).
// AMODE 2: rows=bCnt[bBase+e], ar = bOffA[bBase+e] + m0 + r (contiguous permuted).
// CMODE 0: cr = ar-equivalent index. CMODE 1: cr = rowIdx[bOffA[bBase+e]+m0+r].
// EPI: 0 store(+bias), 1 store*rowScale[cr], 2 += *rowScale[cr].
#define STG 40960
#define GSM_SIZE (2*STG + 512)

template<int AMODE, int CMODE, int EPI>
__global__ __launch_bounds__(256)
void gemm_cp(const __nv_bfloat16* __restrict__ Ah, const __nv_bfloat16* __restrict__ Al,
             int lda, long long aOff,
             const __nv_bfloat16* __restrict__ Wh, const __nv_bfloat16* __restrict__ Wl,
             int ldw, long long wOff,
             const float* __restrict__ bias,
             float* __restrict__ C, int ldc, long long cOff,
             const int* __restrict__ rowIdx, const int* __restrict__ bOffA,
             const int* __restrict__ bCnt, int bBase,
             const float* __restrict__ rowScale,
             int M, int N, int K)
{
    extern __shared__ char smc[];
    const uint32_t smb = smem_to_u32(smc);
    int* rmap = (int*)(smc + 2*STG);

    const int e = blockIdx.z;
    Ah += (long long)e * aOff; Al += (long long)e * aOff;
    Wh += (long long)e * wOff; Wl += (long long)e * wOff;
    C  += (long long)e * cOff;

    int rows = M, aBase = 0;
    if (AMODE == 2) { rows = bCnt[bBase+e]; aBase = bOffA[bBase+e]; }
    const int m0 = blockIdx.y * 128, n0 = blockIdx.x * 128;
    if (m0 >= rows) return;

    const int tid = threadIdx.x, warp = tid >> 5, lane = tid & 31;
    const int wm = warp & 3, wn = warp >> 2;

    if (CMODE == 1 && tid < 128) {
        int r = m0 + tid;
        rmap[tid] = (r < rows) ? rowIdx[aBase + r] : -1;
    }
    if (CMODE == 1) __syncthreads();

    // loaders: thread owns row tid>>1, 32B segment (tid&1)
    const int lrow = tid >> 1;
    const int seg  = tid & 1;
    const bool av = (m0 + lrow) < rows;
    const long long arow = (long long)(aBase + m0 + lrow);
    const __nv_bfloat16* aSrcH = Ah + (av ? arow * lda : 0) + seg*16;
    const __nv_bfloat16* aSrcL = Al + (av ? arow * lda : 0) + seg*16;
    const uint32_t aSz = av ? 16u : 0u;
    const bool nok = (n0 + lrow) < N;
    const __nv_bfloat16* bSrcH = Wh + (nok ? (long long)(n0 + lrow) * ldw : 0) + seg*16;
    const __nv_bfloat16* bSrcL = Wl + (nok ? (long long)(n0 + lrow) * ldw : 0) + seg*16;
    const uint32_t bSz = nok ? 16u : 0u;
    const uint32_t dRow = (uint32_t)lrow*80 + seg*32;

#define LOADS(c) { \
    const int k0 = (c)*32; \
    const uint32_t sb = smb + ((c)&1)*STG; \
    CPA(sb + dRow,              aSrcH + k0,     aSz); \
    CPA(sb + dRow + 16,         aSrcH + k0 + 8, aSz); \
    CPA(sb + 10240 + dRow,      aSrcL + k0,     aSz); \
    CPA(sb + 10240 + dRow + 16, aSrcL + k0 + 8, aSz); \
    CPA(sb + 20480 + dRow,      bSrcH + k0,     bSz); \
    CPA(sb + 20480 + dRow + 16, bSrcH + k0 + 8, bSz); \
    CPA(sb + 30720 + dRow,      bSrcL + k0,     bSz); \
    CPA(sb + 30720 + dRow + 16, bSrcL + k0 + 8, bSz); \
    CPA_COMMIT(); }

    const uint32_t aoff = (uint32_t)(lane & 15)*80 + (((uint32_t)lane >> 4) << 4);
    const uint32_t boff = (uint32_t)((lane & 7) + ((lane >> 4) << 3))*80 + (uint32_t)(((lane >> 3) & 1) << 4);

    float d[2][8][4];
    #pragma unroll
    for (int i = 0; i < 2; i++)
        #pragma unroll
        for (int j = 0; j < 8; j++)
            #pragma unroll
            for (int r = 0; r < 4; r++) d[i][j][r] = 0.f;

#define COMPUTES(buf) { \
    const uint32_t sb = smb + (buf)*STG; \
    _Pragma("unroll") \
    for (int ks = 0; ks < 2; ks++) { \
        uint32_t ah[2][4], al[2][4], bh[4][4], bl[4][4]; \
        _Pragma("unroll") \
        for (int mt = 0; mt < 2; mt++) { \
            uint32_t ad = sb + (uint32_t)(wm*32 + mt*16)*80 + ks*32 + aoff; \
            LDSM4(ah[mt][0], ah[mt][1], ah[mt][2], ah[mt][3], ad); \
            LDSM4(al[mt][0], al[mt][1], al[mt][2], al[mt][3], ad + 10240); \
        } \
        _Pragma("unroll") \
        for (int ng = 0; ng < 4; ng++) { \
            uint32_t bd = sb + 20480 + (uint32_t)(wn*64 + ng*16)*80 + ks*32 + boff; \
            LDSM4(bh[ng][0], bh[ng][1], bh[ng][2], bh[ng][3], bd); \
            LDSM4(bl[ng][0], bl[ng][1], bl[ng][2], bl[ng][3], bd + 10240); \
        } \
        _Pragma("unroll") \
        for (int mt = 0; mt < 2; mt++) \
            _Pragma("unroll") \
            for (int ng = 0; ng < 4; ng++) \
                _Pragma("unroll") \
                for (int h = 0; h < 2; h++) { \
                    float* dd = d[mt][ng*2 + h]; \
                    mma16(dd, ah[mt], &bh[ng][2*h]); \
                    mma16(dd, ah[mt], &bl[ng][2*h]); \
                    mma16(dd, al[mt], &bh[ng][2*h]); \
                } \
    } }

    const int nc = K / 32;
    LOADS(0)
    for (int c = 0; c < nc; c++) {
        CPA_WAIT0();
        __syncthreads();
        if (c + 1 < nc) LOADS(c+1)
        COMPUTES(c & 1)
    }
#undef LOADS
#undef COMPUTES

    // epilogue
    #pragma unroll
    for (int mt = 0; mt < 2; mt++) {
        #pragma unroll
        for (int h = 0; h < 2; h++) {
            int r = wm*32 + mt*16 + (lane >> 2) + 8*h;
            if (m0 + r >= rows) continue;
            int cr = (CMODE == 0) ? (aBase + m0 + r) : rmap[r];
            if (cr < 0) continue;
            float* crow = C + (long long)cr * ldc;
            float sc = (EPI >= 1) ? rowScale[cr] : 0.f;
            #pragma unroll
            for (int n8 = 0; n8 < 8; n8++) {
                int c0 = n0 + wn*64 + n8*8 + (lane & 3)*2;
                if (c0 >= N) continue;
                float v0 = d[mt][n8][2*h + 0];
                float v1 = d[mt][n8][2*h + 1];
                if (EPI == 0) {
                    if (bias) { v0 += bias[c0]; v1 += bias[c0+1]; }
                    *(float2*)(crow + c0) = make_float2(v0, v1);
                } else if (EPI == 1) {
                    *(float2*)(crow + c0) = make_float2(v0*sc, v1*sc);
                } else {
                    float2 o = *(float2*)(crow + c0);
                    *(float2*)(crow + c0) = make_float2(o.x + v0*sc, o.y + v1*sc);
                }
            }
        }
    }
}

// ---------------- attention: 64 queries x (head,batch) per block ------------
#define SMEM_ATTN 220160

__global__ __launch_bounds__(256)
void attn2(const float* __restrict__ Q, const float* __restrict__ K,
           const float* __restrict__ V, float* __restrict__ O)
{
    extern __shared__ float smatt[];
    float* Qs = smatt;
    float* Ks = smatt + 144*64;
    float* Vs = smatt + 144*64 + 144*128;
    float* Ss = Vs + 128*148;

    const int tid = threadIdx.x;
    const int q0 = blockIdx.x * 64;
    const int h = blockIdx.y, b = blockIdx.z;
    const long long qrow0 = (long long)b*1024 + q0;
    const int hc = h*144;

    for (int i = tid; i < 64*36; i += 256) {
        int q = i / 36, f = i % 36;
        float4 v4 = *(const float4*)(Q + (qrow0 + q)*DM + hc + f*4);
        Qs[(f*4+0)*64+q]=v4.x; Qs[(f*4+1)*64+q]=v4.y;
        Qs[(f*4+2)*64+q]=v4.z; Qs[(f*4+3)*64+q]=v4.w;
    }
    for (int i = tid; i < 128*36; i += 256) {
        int k = i / 36, f = i % 36;
        float4 v4 = *(const float4*)(K + ((long long)b*128 + k)*DM + hc + f*4);
        Ks[(f*4+0)*128+k]=v4.x; Ks[(f*4+1)*128+k]=v4.y;
        Ks[(f*4+2)*128+k]=v4.z; Ks[(f*4+3)*128+k]=v4.w;
        float4 w4 = *(const float4*)(V + ((long long)b*128 + k)*DM + hc + f*4);
        *(float4*)&Vs[k*148 + f*4] = w4;
    }
    __syncthreads();

    const int tx = tid & 15, ty = tid >> 4;

    {
        float acc[4][8] = {};
        for (int d = 0; d < 144; d++) {
            float a[4], bv[8];
            *(float4*)a      = *(const float4*)&Qs[d*64 + ty*4];
            *(float4*)bv     = *(const float4*)&Ks[d*128 + tx*8];
            *(float4*)(bv+4) = *(const float4*)&Ks[d*128 + tx*8 + 4];
            #pragma unroll
            for (int i = 0; i < 4; i++)
                #pragma unroll
                for (int j = 0; j < 8; j++) acc[i][j] += a[i]*bv[j];
        }
        #pragma unroll
        for (int i = 0; i < 4; i++)
            #pragma unroll
            for (int j = 0; j < 8; j++)
                Ss[(ty*4+i)*132 + tx*8 + j] = acc[i][j] * (1.0f/12.0f);
    }
    __syncthreads();

    if (tid < 64) {
        float* r = Ss + tid*132;
        float mx = -1e30f;
        for (int k = 0; k < 128; k++) mx = fmaxf(mx, r[k]);
        float sum = 0.f;
        for (int k = 0; k < 128; k++) { float ev = expf(r[k]-mx); r[k] = ev; sum += ev; }
        float inv = 1.0f / sum;
        for (int k = 0; k < 128; k++) r[k] *= inv;
    }
    __syncthreads();

    {
        float o[4][9] = {};
        for (int k = 0; k < 128; k++) {
            float s[4];
            #pragma unroll
            for (int i = 0; i < 4; i++) s[i] = Ss[(ty*4+i)*132 + k];
            #pragma unroll
            for (int j = 0; j < 9; j++) {
                float vv = Vs[k*148 + tx*9 + j];
                #pragma unroll
                for (int i = 0; i < 4; i++) o[i][j] += s[i]*vv;
            }
        }
        #pragma unroll
        for (int i = 0; i < 4; i++)
            #pragma unroll
            for (int j = 0; j < 9; j++)
                O[(qrow0 + ty*4 + i)*DM + hc + tx*9 + j] = o[i][j];
    }
}

// ---------------- small exact kernels ----------------
__global__ void gate4(const float* __restrict__ A, const float* __restrict__ W,
                      const float* __restrict__ b, float* __restrict__ out)
{
    int w = blockIdx.x*8 + (threadIdx.x >> 5);
    int lane = threadIdx.x & 31;
    if (w >= NROW) return;
    const float* a = A + (long long)w*DM;
    float s0=0,s1=0,s2=0,s3=0;
    for (int c = lane*4; c < DM; c += 128) {
        float4 av = *(const float4*)(a + c);
        float4 w0 = *(const float4*)(W + c);
        float4 w1 = *(const float4*)(W + DM + c);
        float4 w2 = *(const float4*)(W + 2*DM + c);
        float4 w3 = *(const float4*)(W + 3*DM + c);
        s0 += av.x*w0.x + av.y*w0.y + av.z*w0.z + av.w*w0.w;
        s1 += av.x*w1.x + av.y*w1.y + av.z*w1.z + av.w*w1.w;
        s2 += av.x*w2.x + av.y*w2.y + av.z*w2.z + av.w*w2.w;
        s3 += av.x*w3.x + av.y*w3.y + av.z*w3.z + av.w*w3.w;
    }
    #pragma unroll
    for (int o = 16; o > 0; o >>= 1) {
        s0 += __shfl_xor_sync(0xffffffffu, s0, o);
        s1 += __shfl_xor_sync(0xffffffffu, s1, o);
        s2 += __shfl_xor_sync(0xffffffffu, s2, o);
        s3 += __shfl_xor_sync(0xffffffffu, s3, o);
    }
    if (lane == 0) {
        out[w*4+0] = s0 + b[0]; out[w*4+1] = s1 + b[1];
        out[w*4+2] = s2 + b[2]; out[w*4+3] = s3 + b[3];
    }
}

__global__ void hlk(const float* __restrict__ t, const float* __restrict__ w,
                    const float* __restrict__ bb, float* __restrict__ hl)
{
    int wi = threadIdx.x >> 5, lane = threadIdx.x & 31;
    int r = wi >> 1, o = wi & 1;
    const float* a = t + r*DM;
    const float* ww = w + o*DM;
    float s = 0.f;
    for (int c = lane*4; c < DM; c += 128) {
        float4 av = *(const float4*)(a + c);
        float4 wv = *(const float4*)(ww + c);
        s += av.x*wv.x + av.y*wv.y + av.z*wv.z + av.w*wv.w;
    }
    #pragma unroll
    for (int off = 16; off > 0; off >>= 1) s += __shfl_xor_sync(0xffffffffu, s, off);
    if (lane == 0) hl[r*2+o] = s + bb[o];
}

// ---------------- gating + routing ----------------
__global__ void init_counts()
{
    if (threadIdx.x < 8) g_cnt[threadIdx.x] = 0;
}

__global__ void gating_kernel(const float* __restrict__ caplog, const float* __restrict__ aclog)
{
    int n = blockIdx.x * blockDim.x + threadIdx.x;
    if (n >= NROW) return;

    uint32_t k1a,k1b,k2a,k2b,k3a,k3b;
    tf2x32(0u, 42u, 0u, 0u, k1a, k1b);
    tf2x32(0u, 42u, 0u, 1u, k2a, k2b);
    tf2x32(0u, 42u, 0u, 2u, k3a, k3b);

    float g0 = gumbel_from_bits(jax_bits_p(k1a, k1b, 2u*(uint32_t)n + 0u));
    float g1 = gumbel_from_bits(jax_bits_p(k1a, k1b, 2u*(uint32_t)n + 1u));
    int bb = n >> 10;
    float l0 = g_hl[2*bb + 0] + g0;
    float l1 = g_hl[2*bb + 1] + g1;
    float mx = fmaxf(l0, l1);
    float e0 = expf(l0 - mx), e1 = expf(l1 - mx);
    float inv = 1.0f / (e0 + e1);
    g_cm[n] = e0 * inv;
    g_am[n] = e1 * inv;

    int be = 0; float bv = -1e30f;
    #pragma unroll
    for (int c = 0; c < 4; c++) {
        float g = gumbel_from_bits(jax_bits_p(k2a, k2b, 4u*(uint32_t)n + (uint32_t)c));
        float yv = caplog[n*4 + c] + g;
        if (yv > bv) { bv = yv; be = c; }
    }
    g_cpe[n] = be;
    atomicAdd(&g_cnt[be], 1);

    int ae = 0; bv = -1e30f;
    #pragma unroll
    for (int c = 0; c < 4; c++) {
        float g = gumbel_from_bits(jax_bits_p(k3a, k3b, 4u*(uint32_t)n + (uint32_t)c));
        float yv = aclog[n*4 + c] + g;
        if (yv > bv) { bv = yv; ae = c; }
    }
    g_ape[n] = ae;
    atomicAdd(&g_cnt[4 + ae], 1);
}

__global__ void offsets_kernel()
{
    int o = 0;
    for (int e = 0; e < 4; e++) { g_off[e] = o; o += g_cnt[e]; }
    o = NROW;
    for (int e = 4; e < 8; e++) { g_off[e] = o; o += g_cnt[e]; }
    for (int j = 0; j < 8; j++) g_cur[j] = g_off[j];
}

__global__ void scatter_kernel()
{
    int n = blockIdx.x * blockDim.x + threadIdx.x;
    if (n >= NROW) return;
    int e = g_cpe[n];
    int p = atomicAdd(&g_cur[e], 1);
    g_idx[p] = n;
    int a = g_ape[n];
    p = atomicAdd(&g_cur[4 + a], 1);
    g_idx[p] = n;
}

// ---------------- lb loss ----------------
__global__ void lb_kernel(float* __restrict__ outp, long long i1)
{
    __shared__ float sh[256 * 9];
    int t = threadIdx.x;
    float u[8] = {0,0,0,0,0,0,0,0};
    float ms = 0.f;
    for (int n = t; n < NROW; n += 256) {
        u[g_cpe[n]]     += g_cm[n];
        u[4 + g_ape[n]] += g_am[n];
        ms += g_cm[n] + g_am[n];
    }
    #pragma unroll
    for (int j = 0; j < 8; j++) sh[t*9 + j] = u[j];
    sh[t*9 + 8] = ms;
    __syncthreads();
    for (int stride = 128; stride > 0; stride >>= 1) {
        if (t < stride)
            #pragma unroll
            for (int j = 0; j < 9; j++) sh[t*9 + j] += sh[(t + stride)*9 + j];
        __syncthreads();
    }
    if (t == 0 && i1 >= 0) {
        float denom = 4.0f * sh[8] + 1e-10f;
        float acc = 0.f;
        for (int j = 0; j < 8; j++) {
            float uu = sh[j] / denom;
            acc += uu * logf(uu + 1e-10f);
        }
        outp[i1] = acc / 8.0f;
    }
}

// ---------------- host launcher ----------------
static inline void cvt(const float* src, __nv_bfloat16* h, __nv_bfloat16* l, long long n)
{
    int n4 = (int)(n / 4);
    cvt_split<<<(n4 + 255)/256, 256>>>((const float4*)src, (uint2*)h, (uint2*)l, n4);
}

extern "C" void kernel_launch(void* const* d_in, const int* in_sizes, int n_in,
                              void* d_out, int out_size)
{
    const float* x        = (const float*)d_in[0];
    const float* timei    = (const float*)d_in[1];
    const float* caption  = (const float*)d_in[2];
    const float* acoustic = (const float*)d_in[3];
    const float* w_in     = (const float*)d_in[4];
    const float* b_in     = (const float*)d_in[5];
    const float* w_out    = (const float*)d_in[6];
    const float* b_out    = (const float*)d_in[7];
    const float* hlw      = (const float*)d_in[8];
    const float* hlb      = (const float*)d_in[9];
    const float* cgw      = (const float*)d_in[10];
    const float* cgb      = (const float*)d_in[11];
    const float* agw      = (const float*)d_in[12];
    const float* agb      = (const float*)d_in[13];
    const float* cw1      = (const float*)d_in[14];
    const float* cw2      = (const float*)d_in[15];
    const float* cw3      = (const float*)d_in[16];
    const float* aw1      = (const float*)d_in[17];
    const float* aw2      = (const float*)d_in[18];
    const float* aw3      = (const float*)d_in[19];
    const float* fw1      = (const float*)d_in[20];
    const float* fw2      = (const float*)d_in[21];
    const float* fw3      = (const float*)d_in[22];
    float* out = (float*)d_out;

    float *pq,*pk,*pv,*pca,*pcap2,*pclog,*palog,*phl,*pcm,*pam,*pH,*pR,*py;
    int *pidx,*poff,*pcnt;
    __nv_bfloat16 *xh,*xl,*gxh,*gxl,*cph,*cpl,*winh,*winl,*wouth,*woutl,*ewh,*ewl;
    __nv_bfloat16 *cah,*cal,*Hh,*Hl,*yh,*yl,*Rh,*Rl;

    cudaGetSymbolAddress((void**)&pq,    g_q);
    cudaGetSymbolAddress((void**)&pk,    g_k);
    cudaGetSymbolAddress((void**)&pv,    g_v);
    cudaGetSymbolAddress((void**)&pca,   g_ca);
    cudaGetSymbolAddress((void**)&pcap2, g_cap2);
    cudaGetSymbolAddress((void**)&pclog, g_caplog);
    cudaGetSymbolAddress((void**)&palog, g_aclog);
    cudaGetSymbolAddress((void**)&phl,   g_hl);
    cudaGetSymbolAddress((void**)&pcm,   g_cm);
    cudaGetSymbolAddress((void**)&pam,   g_am);
    cudaGetSymbolAddress((void**)&pH,    g_H);
    cudaGetSymbolAddress((void**)&pR,    g_R);
    cudaGetSymbolAddress((void**)&py,    g_y);
    cudaGetSymbolAddress((void**)&pidx,  g_idx);
    cudaGetSymbolAddress((void**)&poff,  g_off);
    cudaGetSymbolAddress((void**)&pcnt,  g_cnt);
    cudaGetSymbolAddress((void**)&xh,    g_xh);
    cudaGetSymbolAddress((void**)&xl,    g_xl);
    cudaGetSymbolAddress((void**)&gxh,   g_gxh);
    cudaGetSymbolAddress((void**)&gxl,   g_gxl);
    cudaGetSymbolAddress((void**)&cph,   g_caph);
    cudaGetSymbolAddress((void**)&cpl,   g_capl);
    cudaGetSymbolAddress((void**)&winh,  g_winh);
    cudaGetSymbolAddress((void**)&winl,  g_winl);
    cudaGetSymbolAddress((void**)&wouth, g_wouth);
    cudaGetSymbolAddress((void**)&woutl, g_woutl);
    cudaGetSymbolAddress((void**)&ewh,   g_ewh);
    cudaGetSymbolAddress((void**)&ewl,   g_ewl);
    cudaGetSymbolAddress((void**)&cah,   g_cah);
    cudaGetSymbolAddress((void**)&cal,   g_cal);
    cudaGetSymbolAddress((void**)&Hh,    g_Hh);
    cudaGetSymbolAddress((void**)&Hl,    g_Hl);
    cudaGetSymbolAddress((void**)&yh,    g_yh);
    cudaGetSymbolAddress((void**)&yl,    g_yl);
    cudaGetSymbolAddress((void**)&Rh,    g_Rh);
    cudaGetSymbolAddress((void**)&Rl,    g_Rl);

    cudaFuncSetAttribute(attn2, cudaFuncAttributeMaxDynamicSharedMemorySize, SMEM_ATTN);
    cudaFuncSetAttribute(gemm_cp<0,0,0>, cudaFuncAttributeMaxDynamicSharedMemorySize, GSM_SIZE);
    cudaFuncSetAttribute(gemm_cp<2,0,0>, cudaFuncAttributeMaxDynamicSharedMemorySize, GSM_SIZE);
    cudaFuncSetAttribute(gemm_cp<2,1,1>, cudaFuncAttributeMaxDynamicSharedMemorySize, GSM_SIZE);
    cudaFuncSetAttribute(gemm_cp<2,1,2>, cudaFuncAttributeMaxDynamicSharedMemorySize, GSM_SIZE);

    const int n4per = HDM/4;

    // 1-4) input/attn weight conversions
    cvt(x,       xh,   xl,   (long long)NROW*DM);
    cvt(caption, cph,  cpl,  (long long)SKV*DM);
    cvt(w_in,    winh, winl, 3LL*DM*DM);
    cvt(w_out,   wouth,woutl,(long long)DM*DM);
    // 5) gemm K  (launch #5)
    gemm_cp<0,0,0><<<dim3(9,2,1),256,GSM_SIZE>>>(cph, cpl, DM, 0, winh + (long long)DM*DM, winl + (long long)DM*DM, DM, 0, b_in + DM,
        pk, DM, 0, nullptr,nullptr,nullptr,0, nullptr, SKV, DM, DM);
    // 6) gemm Q  (launch #6 — ncu -s5 captures this)
    gemm_cp<0,0,0><<<dim3(9,16,1),256,GSM_SIZE>>>(xh, xl, DM, 0, winh, winl, DM, 0, b_in,
        pq, DM, 0, nullptr,nullptr,nullptr,0, nullptr, NROW, DM, DM);
    // 7) gemm V
    gemm_cp<0,0,0><<<dim3(9,2,1),256,GSM_SIZE>>>(cph, cpl, DM, 0, winh + 2LL*DM*DM, winl + 2LL*DM*DM, DM, 0, b_in + 2*DM,
        pv, DM, 0, nullptr,nullptr,nullptr,0, nullptr, SKV, DM, DM);
    // 8) attention
    attn2<<<dim3(16,8,2),256,SMEM_ATTN>>>(pq, pk, pv, pca);
    // 9-10) out proj
    cvt(pca, cah, cal, (long long)NROW*DM);
    gemm_cp<0,0,0><<<dim3(9,16,1),256,GSM_SIZE>>>(cah, cal, DM, 0, wouth, woutl, DM, 0, b_out,
        pcap2, DM, 0, nullptr,nullptr,nullptr,0, nullptr, NROW, DM, DM);
    // 11-13) hl + gate logits (exact fp32)
    hlk<<<1,128>>>(timei, hlw, hlb, phl);
    gate4<<<NROW/8,256>>>(pcap2, cgw, cgb, pclog);
    gate4<<<NROW/8,256>>>(acoustic, agw, agb, palog);
    // 14-17) gating + routing
    init_counts<<<1,32>>>();
    gating_kernel<<<8,256>>>(pclog, palog);
    offsets_kernel<<<1,1>>>();
    scatter_kernel<<<8,256>>>();
    // 18-23) expert weight conversions into slots
    // slots: 0-7 [cw1_e|cw3_e]x4, 8-15 [aw1_e|aw3_e]x4, 16-19 cw2, 20-23 aw2,
    //        24-31 [fw1_e|fw3_e]x4, 32-35 fw2
    dim3 pg((n4per + 255)/256, 1, 4);
    cvt_pair<<<pg,256>>>((const float4*)cw1, (const float4*)cw3,
                         (uint2*)(ewh + 0LL*HDM),  (uint2*)(ewl + 0LL*HDM),  n4per);
    cvt_pair<<<pg,256>>>((const float4*)aw1, (const float4*)aw3,
                         (uint2*)(ewh + 8LL*HDM),  (uint2*)(ewl + 8LL*HDM),  n4per);
    cvt(cw2, ewh + 16LL*HDM, ewl + 16LL*HDM, 4LL*HDM);
    cvt(aw2, ewh + 20LL*HDM, ewl + 20LL*HDM, 4LL*HDM);
    cvt_pair<<<pg,256>>>((const float4*)fw1, (const float4*)fw3,
                         (uint2*)(ewh + 24LL*HDM), (uint2*)(ewl + 24LL*HDM), n4per);
    cvt(fw2, ewh + 32LL*HDM, ewl + 32LL*HDM, 4LL*HDM);
    // 24) permute x rows into bucket order (4096 rows: cap 0-2047, ac 2048-4095)
    permute_x<<<2*NROW,128>>>((const uint4*)xh, (const uint4*)xl, (uint4*)gxh, (uint4*)gxl);
    // 25) MoE up: one GEMM, z=8 buckets, N=1536 (h1|h3), contiguous in/out
    gemm_cp<2,0,0><<<dim3(12,16,8),256,GSM_SIZE>>>(gxh, gxl, DM, 0,
        ewh, ewl, DM, 2LL*HDM, nullptr,
        pH, 1536, 0, nullptr, poff, pcnt, 0, nullptr, NROW, 1536, DM);
    // 26) silu*mul + split (4096 rows)
    silumul_pair<<<(4096*192 + 255)/256,256>>>((const float4*)pH, (uint2*)Hh, (uint2*)Hl, 4096*192);
    // 27) MoE down cap: scatter-store * cm
    gemm_cp<2,1,1><<<dim3(9,16,4),256,GSM_SIZE>>>(Hh, Hl, HIDN, 0,
        ewh + 16LL*HDM, ewl + 16LL*HDM, HIDN, (long long)HDM, nullptr,
        py, DM, 0, pidx, poff, pcnt, 0, pcm, NROW, DM, HIDN);
    // 28) MoE down ac: scatter-accumulate * am
    gemm_cp<2,1,2><<<dim3(9,16,4),256,GSM_SIZE>>>(Hh, Hl, HIDN, 0,
        ewh + 20LL*HDM, ewl + 20LL*HDM, HIDN, (long long)HDM, nullptr,
        py, DM, 0, pidx, poff, pcnt, 4, pam, NROW, DM, HIDN);
    // 29) region FF input conversion
    cvt(py, yh, yl, (long long)NROW*DM);
    // 30) region up: one GEMM z=4, N=1536, column-slice trick on A and W
    gemm_cp<0,0,0><<<dim3(12,16,4),256,GSM_SIZE>>>(yh, yl, DM, REG,
        ewh + 24LL*HDM, ewl + 24LL*HDM, DM, 2LL*HDM + REG, nullptr,
        pR, 1536, 2048LL*1536, nullptr,nullptr,nullptr,0, nullptr, NROW, 1536, REG);
    // 31) silu*mul + split (8192 rows)
    silumul_pair<<<(8192*192 + 255)/256,256>>>((const float4*)pR, (uint2*)Rh, (uint2*)Rl, 8192*192);
    // 32) region down into output column slices
    gemm_cp<0,0,0><<<dim3(3,16,4),256,GSM_SIZE>>>(Rh, Rl, HIDN, 2048LL*HIDN,
        ewh + 32LL*HDM, ewl + 32LL*HDM, HIDN, (long long)HDM + (long long)REG*HIDN, nullptr,
        out, DM, REG, nullptr,nullptr,nullptr,0, nullptr, NROW, REG, HIDN);
    // 33) lb loss scalar
    long long zElems = (long long)NROW * DM;
    long long i1 = ((long long)out_size > zElems) ? zElems : -1;
    lb_kernel<<<1,256>>>(out, i1);
}

// round 10
// speedup vs baseline: 2.3000x; 1.3689x over previous
#include <cuda_runtime.h>
#include <cuda_fp16.h>
#include <cstdint>

#define NROW 2048
#define DM   1152
#define SKV  256
#define HIDN 768
#define REG  288            // DM/4
#define HDM  (HIDN*DM)      // one expert matrix (either orientation)

// ---------------- scratch (device globals; allocation-free) ----------------
__device__ float g_q[NROW*DM];
__device__ float g_k[SKV*DM];
__device__ float g_v[SKV*DM];
__device__ float g_ca[NROW*DM];
__device__ float g_cap2[NROW*DM];
__device__ float g_caplog[NROW*4];
__device__ float g_aclog[NROW*4];
__device__ float g_hl[4];
__device__ float g_cm[NROW];
__device__ float g_am[NROW];
__device__ int   g_cpe[NROW];
__device__ int   g_ape[NROW];
__device__ int   g_cnt[8];
__device__ int   g_off[8];
__device__ int   g_cur[8];
__device__ int   g_idx[2*NROW];          // perm position -> original row
__device__ float g_H[4096L*1536];        // MoE up combined (h1|h3), perm order
__device__ float g_R[8192L*1536];        // region up combined
__device__ float g_y[NROW*DM];

// fp16 operands: activations hi/lo (A side), weights single fp16 (B side)
__device__ __half g_xh[NROW*DM],  g_xl[NROW*DM];
__device__ __half g_gxh[2*NROW*DM], g_gxl[2*NROW*DM];
__device__ __half g_caph[SKV*DM], g_capl[SKV*DM];
__device__ __half g_win16[3*DM*DM];
__device__ __half g_wout16[DM*DM];
__device__ __half g_ew16[36L*HDM];
__device__ __half g_cah[NROW*DM], g_cal[NROW*DM];
__device__ __half g_Hh[4096L*HIDN], g_Hl[4096L*HIDN];
__device__ __half g_yh[NROW*DM],  g_yl[NROW*DM];
__device__ __half g_Rh[8192L*HIDN], g_Rl[8192L*HIDN];

// ---------------- helpers ----------------
__device__ __forceinline__ uint32_t smem_to_u32(const void* p) {
    uint32_t a;
    asm("{ .reg .u64 t; cvta.to.shared.u64 t, %1; cvt.u32.u64 %0, t; }" : "=r"(a) : "l"(p));
    return a;
}

#define CPA(dst, src, sz) \
    asm volatile("cp.async.cg.shared.global [%0], [%1], 16, %2;" \
                 :: "r"(dst), "l"(src), "r"(sz) : "memory")
#define CPA_COMMIT() asm volatile("cp.async.commit_group;" ::: "memory")
#define CPA_WAIT1()  asm volatile("cp.async.wait_group 1;" ::: "memory")
#define CPA_WAIT0()  asm volatile("cp.async.wait_group 0;" ::: "memory")

#define LDSM4(r0, r1, r2, r3, addr) \
    asm volatile("ldmatrix.sync.aligned.m8n8.x4.shared.b16 {%0,%1,%2,%3}, [%4];" \
                 : "=r"(r0), "=r"(r1), "=r"(r2), "=r"(r3) : "r"(addr))

__device__ __forceinline__ void mma16f(float* d, const uint32_t* a, const uint32_t* b)
{
    asm volatile(
        "mma.sync.aligned.m16n8k16.row.col.f32.f16.f16.f32 "
        "{%0,%1,%2,%3}, {%4,%5,%6,%7}, {%8,%9}, {%0,%1,%2,%3};\n"
        : "+f"(d[0]), "+f"(d[1]), "+f"(d[2]), "+f"(d[3])
        : "r"(a[0]), "r"(a[1]), "r"(a[2]), "r"(a[3]), "r"(b[0]), "r"(b[1]));
}

// ---------------- threefry2x32-20 (exact JAX, partitionable) ----------------
__device__ __forceinline__ uint32_t rotl32(uint32_t v, int r){ return (v<<r)|(v>>(32-r)); }

__device__ __forceinline__ void tf2x32(uint32_t k0, uint32_t k1, uint32_t x0, uint32_t x1,
                                       uint32_t& o0, uint32_t& o1)
{
    uint32_t ks2 = k0 ^ k1 ^ 0x1BD11BDAu;
    x0 += k0; x1 += k1;
#define TFR(r) { x0 += x1; x1 = rotl32(x1,(r)); x1 ^= x0; }
    TFR(13) TFR(15) TFR(26) TFR(6)   x0 += k1;  x1 += ks2 + 1u;
    TFR(17) TFR(29) TFR(16) TFR(24)  x0 += ks2; x1 += k0  + 2u;
    TFR(13) TFR(15) TFR(26) TFR(6)   x0 += k0;  x1 += k1  + 3u;
    TFR(17) TFR(29) TFR(16) TFR(24)  x0 += k1;  x1 += ks2 + 4u;
    TFR(13) TFR(15) TFR(26) TFR(6)   x0 += ks2; x1 += k0  + 5u;
#undef TFR
    o0 = x0; o1 = x1;
}

__device__ __forceinline__ uint32_t jax_bits_p(uint32_t k0, uint32_t k1, uint32_t i)
{
    uint32_t o0, o1;
    tf2x32(k0, k1, 0u, i, o0, o1);
    return o0 ^ o1;
}

__device__ __forceinline__ float gumbel_from_bits(uint32_t bits)
{
    uint32_t fb = (bits >> 9) | 0x3f800000u;
    float f = __uint_as_float(fb) - 1.0f;
    const float TINY = 1.17549435e-38f;
    float u = (f > 0.0f) ? f : TINY;
    return -logf(-logf(u));
}

// ---------------- conversion kernels ----------------
__device__ __forceinline__ void split4h(float4 f, uint2& hi, uint2& lo)
{
    __half2 h0 = __floats2half2_rn(f.x, f.y);
    __half2 h1 = __floats2half2_rn(f.z, f.w);
    float r0 = f.x - __half2float(__low2half(h0));
    float r1 = f.y - __half2float(__high2half(h0));
    float r2 = f.z - __half2float(__low2half(h1));
    float r3 = f.w - __half2float(__high2half(h1));
    __half2 l0 = __floats2half2_rn(r0, r1);
    __half2 l1 = __floats2half2_rn(r2, r3);
    hi = make_uint2(*(uint32_t*)&h0, *(uint32_t*)&h1);
    lo = make_uint2(*(uint32_t*)&l0, *(uint32_t*)&l1);
}

__device__ __forceinline__ uint2 pack4h(float4 f)
{
    __half2 h0 = __floats2half2_rn(f.x, f.y);
    __half2 h1 = __floats2half2_rn(f.z, f.w);
    return make_uint2(*(uint32_t*)&h0, *(uint32_t*)&h1);
}

// activations: fp32 -> fp16 hi + fp16 lo
__global__ void cvt_a16(const float4* __restrict__ src, uint2* __restrict__ hi,
                        uint2* __restrict__ lo, int n4)
{
    int i = blockIdx.x*blockDim.x + threadIdx.x;
    if (i >= n4) return;
    uint2 h, l;
    split4h(src[i], h, l);
    hi[i] = h; lo[i] = l;
}

// weights: fp32 -> fp16 single
__global__ void cvt_w16(const float4* __restrict__ src, uint2* __restrict__ dst, int n4)
{
    int i = blockIdx.x*blockDim.x + threadIdx.x;
    if (i >= n4) return;
    dst[i] = pack4h(src[i]);
}

// w1/w3 expert pair -> interleaved slots (single fp16)
__global__ void cvt_pair16(const float4* __restrict__ s1, const float4* __restrict__ s2,
                           uint2* __restrict__ dst, int n4per)
{
    int e = blockIdx.z;
    int i = blockIdx.x*blockDim.x + threadIdx.x;
    if (i >= n4per) return;
    dst[(long long)(2*e)*n4per + i]   = pack4h(s1[(long long)e*n4per + i]);
    dst[(long long)(2*e+1)*n4per + i] = pack4h(s2[(long long)e*n4per + i]);
}

// silu(h1)*h3 from combined [rows][1536] -> fp16 hi/lo [rows][768]
__global__ void silumul_pair16(const float4* __restrict__ H, uint2* __restrict__ hi,
                               uint2* __restrict__ lo, int total)  // total = rows*192
{
    int i = blockIdx.x*blockDim.x + threadIdx.x;
    if (i >= total) return;
    int row = i / 192, j = i % 192;
    float4 a = H[(long long)row*384 + j];
    float4 c = H[(long long)row*384 + 192 + j];
    float4 r;
    r.x = a.x/(1.f+expf(-a.x))*c.x;
    r.y = a.y/(1.f+expf(-a.y))*c.y;
    r.z = a.z/(1.f+expf(-a.z))*c.z;
    r.w = a.w/(1.f+expf(-a.w))*c.w;
    uint2 h, l;
    split4h(r, h, l);
    hi[i] = h; lo[i] = l;
}

// gather x rows into permuted (bucket-contiguous) order (fp16 rows: 144 uint4)
__global__ void permute_x(const uint4* __restrict__ xh, const uint4* __restrict__ xl,
                          uint4* __restrict__ gh, uint4* __restrict__ gl)
{
    const int W16 = DM*2/16;  // 144
    int p = blockIdx.x;
    int src = g_idx[p];
    for (int c = threadIdx.x; c < W16; c += blockDim.x) {
        gh[(long long)p*W16 + c] = xh[(long long)src*W16 + c];
        gl[(long long)p*W16 + c] = xl[(long long)src*W16 + c];
    }
}

// ---------------- fp16-split warp-MMA GEMM (2-term, 3-stage cp.async) -------
// C[cr][n] = sum_k A[ar][k]*W[n][k]; tiles 128x128x32, 256 threads, 8 warps
// (warp tile 32m x 64n). D += ah*bh + al*bh = a*bh (exact); err = a*(b-bh).
// AMODE 0: rows=M, ar = m0+r. AMODE 2: rows=bCnt[e], ar = bOff[e]+m0+r.
// CMODE 0: cr = ar index. CMODE 1: cr = rowIdx[...]. EPI: 0 store(+bias),
// 1 store*rowScale[cr], 2 += *rowScale[cr].
#define STG 30720                 // Ah 10240 | Al 10240 | B 10240 per stage
#define GSM_SIZE (3*STG + 512)

template<int AMODE, int CMODE, int EPI>
__global__ __launch_bounds__(256)
void gemm_cp(const __half* __restrict__ Ah, const __half* __restrict__ Al,
             int lda, long long aOff,
             const __half* __restrict__ W, int ldw, long long wOff,
             const float* __restrict__ bias,
             float* __restrict__ C, int ldc, long long cOff,
             const int* __restrict__ rowIdx, const int* __restrict__ bOffA,
             const int* __restrict__ bCnt, int bBase,
             const float* __restrict__ rowScale,
             int M, int N, int K)
{
    extern __shared__ char smc[];
    const uint32_t smb = smem_to_u32(smc);
    int* rmap = (int*)(smc + 3*STG);

    const int e = blockIdx.z;
    Ah += (long long)e * aOff; Al += (long long)e * aOff;
    W  += (long long)e * wOff;
    C  += (long long)e * cOff;

    int rows = M, aBase = 0;
    if (AMODE == 2) { rows = bCnt[bBase+e]; aBase = bOffA[bBase+e]; }
    const int m0 = blockIdx.y * 128, n0 = blockIdx.x * 128;
    if (m0 >= rows) return;

    const int tid = threadIdx.x, warp = tid >> 5, lane = tid & 31;
    const int wm = warp & 3, wn = warp >> 2;

    if (CMODE == 1 && tid < 128) {
        int r = m0 + tid;
        rmap[tid] = (r < rows) ? rowIdx[aBase + r] : -1;
    }
    if (CMODE == 1) __syncthreads();

    // loaders: thread owns row tid>>1, 32B segment (tid&1); 64B per row per matrix
    const int lrow = tid >> 1;
    const int seg  = tid & 1;
    const bool av = (m0 + lrow) < rows;
    const long long arow = (long long)(aBase + m0 + lrow);
    const __half* aSrcH = Ah + (av ? arow * lda : 0) + seg*16;
    const __half* aSrcL = Al + (av ? arow * lda : 0) + seg*16;
    const uint32_t aSz = av ? 16u : 0u;
    const bool nok = (n0 + lrow) < N;
    const __half* bSrc = W + (nok ? (long long)(n0 + lrow) * ldw : 0) + seg*16;
    const uint32_t bSz = nok ? 16u : 0u;
    const uint32_t dRow = (uint32_t)lrow*80 + seg*32;

#define LOADS(c) { \
    const int k0 = (c)*32; \
    const uint32_t sb = smb + ((c)%3)*STG; \
    CPA(sb + dRow,              aSrcH + k0,     aSz); \
    CPA(sb + dRow + 16,         aSrcH + k0 + 8, aSz); \
    CPA(sb + 10240 + dRow,      aSrcL + k0,     aSz); \
    CPA(sb + 10240 + dRow + 16, aSrcL + k0 + 8, aSz); \
    CPA(sb + 20480 + dRow,      bSrc  + k0,     bSz); \
    CPA(sb + 20480 + dRow + 16, bSrc  + k0 + 8, bSz); \
    CPA_COMMIT(); }

    const uint32_t aoff = (uint32_t)(lane & 15)*80 + (((uint32_t)lane >> 4) << 4);
    const uint32_t boff = (uint32_t)((lane & 7) + ((lane >> 4) << 3))*80 + (uint32_t)(((lane >> 3) & 1) << 4);

    float d[2][8][4];
    #pragma unroll
    for (int i = 0; i < 2; i++)
        #pragma unroll
        for (int j = 0; j < 8; j++)
            #pragma unroll
            for (int r = 0; r < 4; r++) d[i][j][r] = 0.f;

#define COMPUTES(buf) { \
    const uint32_t sb = smb + (buf)*STG; \
    _Pragma("unroll") \
    for (int ks = 0; ks < 2; ks++) { \
        uint32_t ah[2][4], al[2][4], bh[4][4]; \
        _Pragma("unroll") \
        for (int mt = 0; mt < 2; mt++) { \
            uint32_t ad = sb + (uint32_t)(wm*32 + mt*16)*80 + ks*32 + aoff; \
            LDSM4(ah[mt][0], ah[mt][1], ah[mt][2], ah[mt][3], ad); \
            LDSM4(al[mt][0], al[mt][1], al[mt][2], al[mt][3], ad + 10240); \
        } \
        _Pragma("unroll") \
        for (int ng = 0; ng < 4; ng++) { \
            uint32_t bd = sb + 20480 + (uint32_t)(wn*64 + ng*16)*80 + ks*32 + boff; \
            LDSM4(bh[ng][0], bh[ng][1], bh[ng][2], bh[ng][3], bd); \
        } \
        _Pragma("unroll") \
        for (int mt = 0; mt < 2; mt++) \
            _Pragma("unroll") \
            for (int ng = 0; ng < 4; ng++) \
                _Pragma("unroll") \
                for (int h = 0; h < 2; h++) { \
                    float* dd = d[mt][ng*2 + h]; \
                    mma16f(dd, ah[mt], &bh[ng][2*h]); \
                    mma16f(dd, al[mt], &bh[ng][2*h]); \
                } \
    } }

    const int nc = K / 32;
    LOADS(0)
    if (nc > 1) LOADS(1)
    for (int c = 0; c < nc; c++) {
        if (c + 1 < nc) { CPA_WAIT1(); } else { CPA_WAIT0(); }
        __syncthreads();
        if (c + 2 < nc) LOADS(c+2)
        COMPUTES(c % 3)
    }
#undef LOADS
#undef COMPUTES

    // epilogue
    #pragma unroll
    for (int mt = 0; mt < 2; mt++) {
        #pragma unroll
        for (int h = 0; h < 2; h++) {
            int r = wm*32 + mt*16 + (lane >> 2) + 8*h;
            if (m0 + r >= rows) continue;
            int cr = (CMODE == 0) ? (aBase + m0 + r) : rmap[r];
            if (cr < 0) continue;
            float* crow = C + (long long)cr * ldc;
            float sc = (EPI >= 1) ? rowScale[cr] : 0.f;
            #pragma unroll
            for (int n8 = 0; n8 < 8; n8++) {
                int c0 = n0 + wn*64 + n8*8 + (lane & 3)*2;
                if (c0 >= N) continue;
                float v0 = d[mt][n8][2*h + 0];
                float v1 = d[mt][n8][2*h + 1];
                if (EPI == 0) {
                    if (bias) { v0 += bias[c0]; v1 += bias[c0+1]; }
                    *(float2*)(crow + c0) = make_float2(v0, v1);
                } else if (EPI == 1) {
                    *(float2*)(crow + c0) = make_float2(v0*sc, v1*sc);
                } else {
                    float2 o = *(float2*)(crow + c0);
                    *(float2*)(crow + c0) = make_float2(o.x + v0*sc, o.y + v1*sc);
                }
            }
        }
    }
}

// ---------------- attention: 64 queries x (head,batch) per block ------------
#define SMEM_ATTN 220160

__global__ __launch_bounds__(256)
void attn2(const float* __restrict__ Q, const float* __restrict__ K,
           const float* __restrict__ V, float* __restrict__ O)
{
    extern __shared__ float smatt[];
    float* Qs = smatt;
    float* Ks = smatt + 144*64;
    float* Vs = smatt + 144*64 + 144*128;
    float* Ss = Vs + 128*148;

    const int tid = threadIdx.x;
    const int q0 = blockIdx.x * 64;
    const int h = blockIdx.y, b = blockIdx.z;
    const long long qrow0 = (long long)b*1024 + q0;
    const int hc = h*144;

    for (int i = tid; i < 64*36; i += 256) {
        int q = i / 36, f = i % 36;
        float4 v4 = *(const float4*)(Q + (qrow0 + q)*DM + hc + f*4);
        Qs[(f*4+0)*64+q]=v4.x; Qs[(f*4+1)*64+q]=v4.y;
        Qs[(f*4+2)*64+q]=v4.z; Qs[(f*4+3)*64+q]=v4.w;
    }
    for (int i = tid; i < 128*36; i += 256) {
        int k = i / 36, f = i % 36;
        float4 v4 = *(const float4*)(K + ((long long)b*128 + k)*DM + hc + f*4);
        Ks[(f*4+0)*128+k]=v4.x; Ks[(f*4+1)*128+k]=v4.y;
        Ks[(f*4+2)*128+k]=v4.z; Ks[(f*4+3)*128+k]=v4.w;
        float4 w4 = *(const float4*)(V + ((long long)b*128 + k)*DM + hc + f*4);
        *(float4*)&Vs[k*148 + f*4] = w4;
    }
    __syncthreads();

    const int tx = tid & 15, ty = tid >> 4;

    {
        float acc[4][8] = {};
        for (int d = 0; d < 144; d++) {
            float a[4], bv[8];
            *(float4*)a      = *(const float4*)&Qs[d*64 + ty*4];
            *(float4*)bv     = *(const float4*)&Ks[d*128 + tx*8];
            *(float4*)(bv+4) = *(const float4*)&Ks[d*128 + tx*8 + 4];
            #pragma unroll
            for (int i = 0; i < 4; i++)
                #pragma unroll
                for (int j = 0; j < 8; j++) acc[i][j] += a[i]*bv[j];
        }
        #pragma unroll
        for (int i = 0; i < 4; i++)
            #pragma unroll
            for (int j = 0; j < 8; j++)
                Ss[(ty*4+i)*132 + tx*8 + j] = acc[i][j] * (1.0f/12.0f);
    }
    __syncthreads();

    if (tid < 64) {
        float* r = Ss + tid*132;
        float mx = -1e30f;
        for (int k = 0; k < 128; k++) mx = fmaxf(mx, r[k]);
        float sum = 0.f;
        for (int k = 0; k < 128; k++) { float ev = expf(r[k]-mx); r[k] = ev; sum += ev; }
        float inv = 1.0f / sum;
        for (int k = 0; k < 128; k++) r[k] *= inv;
    }
    __syncthreads();

    {
        float o[4][9] = {};
        for (int k = 0; k < 128; k++) {
            float s[4];
            #pragma unroll
            for (int i = 0; i < 4; i++) s[i] = Ss[(ty*4+i)*132 + k];
            #pragma unroll
            for (int j = 0; j < 9; j++) {
                float vv = Vs[k*148 + tx*9 + j];
                #pragma unroll
                for (int i = 0; i < 4; i++) o[i][j] += s[i]*vv;
            }
        }
        #pragma unroll
        for (int i = 0; i < 4; i++)
            #pragma unroll
            for (int j = 0; j < 9; j++)
                O[(qrow0 + ty*4 + i)*DM + hc + tx*9 + j] = o[i][j];
    }
}

// ---------------- small exact kernels ----------------
__global__ void gate4(const float* __restrict__ A, const float* __restrict__ W,
                      const float* __restrict__ b, float* __restrict__ out)
{
    int w = blockIdx.x*8 + (threadIdx.x >> 5);
    int lane = threadIdx.x & 31;
    if (w >= NROW) return;
    const float* a = A + (long long)w*DM;
    float s0=0,s1=0,s2=0,s3=0;
    for (int c = lane*4; c < DM; c += 128) {
        float4 av = *(const float4*)(a + c);
        float4 w0 = *(const float4*)(W + c);
        float4 w1 = *(const float4*)(W + DM + c);
        float4 w2 = *(const float4*)(W + 2*DM + c);
        float4 w3 = *(const float4*)(W + 3*DM + c);
        s0 += av.x*w0.x + av.y*w0.y + av.z*w0.z + av.w*w0.w;
        s1 += av.x*w1.x + av.y*w1.y + av.z*w1.z + av.w*w1.w;
        s2 += av.x*w2.x + av.y*w2.y + av.z*w2.z + av.w*w2.w;
        s3 += av.x*w3.x + av.y*w3.y + av.z*w3.z + av.w*w3.w;
    }
    #pragma unroll
    for (int o = 16; o > 0; o >>= 1) {
        s0 += __shfl_xor_sync(0xffffffffu, s0, o);
        s1 += __shfl_xor_sync(0xffffffffu, s1, o);
        s2 += __shfl_xor_sync(0xffffffffu, s2, o);
        s3 += __shfl_xor_sync(0xffffffffu, s3, o);
    }
    if (lane == 0) {
        out[w*4+0] = s0 + b[0]; out[w*4+1] = s1 + b[1];
        out[w*4+2] = s2 + b[2]; out[w*4+3] = s3 + b[3];
    }
}

__global__ void hlk(const float* __restrict__ t, const float* __restrict__ w,
                    const float* __restrict__ bb, float* __restrict__ hl)
{
    int wi = threadIdx.x >> 5, lane = threadIdx.x & 31;
    int r = wi >> 1, o = wi & 1;
    const float* a = t + r*DM;
    const float* ww = w + o*DM;
    float s = 0.f;
    for (int c = lane*4; c < DM; c += 128) {
        float4 av = *(const float4*)(a + c);
        float4 wv = *(const float4*)(ww + c);
        s += av.x*wv.x + av.y*wv.y + av.z*wv.z + av.w*wv.w;
    }
    #pragma unroll
    for (int off = 16; off > 0; off >>= 1) s += __shfl_xor_sync(0xffffffffu, s, off);
    if (lane == 0) hl[r*2+o] = s + bb[o];
}

// ---------------- gating + routing ----------------
__global__ void init_counts()
{
    if (threadIdx.x < 8) g_cnt[threadIdx.x] = 0;
}

__global__ void gating_kernel(const float* __restrict__ caplog, const float* __restrict__ aclog)
{
    int n = blockIdx.x * blockDim.x + threadIdx.x;
    if (n >= NROW) return;

    uint32_t k1a,k1b,k2a,k2b,k3a,k3b;
    tf2x32(0u, 42u, 0u, 0u, k1a, k1b);
    tf2x32(0u, 42u, 0u, 1u, k2a, k2b);
    tf2x32(0u, 42u, 0u, 2u, k3a, k3b);

    float g0 = gumbel_from_bits(jax_bits_p(k1a, k1b, 2u*(uint32_t)n + 0u));
    float g1 = gumbel_from_bits(jax_bits_p(k1a, k1b, 2u*(uint32_t)n + 1u));
    int bb = n >> 10;
    float l0 = g_hl[2*bb + 0] + g0;
    float l1 = g_hl[2*bb + 1] + g1;
    float mx = fmaxf(l0, l1);
    float e0 = expf(l0 - mx), e1 = expf(l1 - mx);
    float inv = 1.0f / (e0 + e1);
    g_cm[n] = e0 * inv;
    g_am[n] = e1 * inv;

    int be = 0; float bv = -1e30f;
    #pragma unroll
    for (int c = 0; c < 4; c++) {
        float g = gumbel_from_bits(jax_bits_p(k2a, k2b, 4u*(uint32_t)n + (uint32_t)c));
        float yv = caplog[n*4 + c] + g;
        if (yv > bv) { bv = yv; be = c; }
    }
    g_cpe[n] = be;
    atomicAdd(&g_cnt[be], 1);

    int ae = 0; bv = -1e30f;
    #pragma unroll
    for (int c = 0; c < 4; c++) {
        float g = gumbel_from_bits(jax_bits_p(k3a, k3b, 4u*(uint32_t)n + (uint32_t)c));
        float yv = aclog[n*4 + c] + g;
        if (yv > bv) { bv = yv; ae = c; }
    }
    g_ape[n] = ae;
    atomicAdd(&g_cnt[4 + ae], 1);
}

__global__ void offsets_kernel()
{
    int o = 0;
    for (int e = 0; e < 4; e++) { g_off[e] = o; o += g_cnt[e]; }
    o = NROW;
    for (int e = 4; e < 8; e++) { g_off[e] = o; o += g_cnt[e]; }
    for (int j = 0; j < 8; j++) g_cur[j] = g_off[j];
}

__global__ void scatter_kernel()
{
    int n = blockIdx.x * blockDim.x + threadIdx.x;
    if (n >= NROW) return;
    int e = g_cpe[n];
    int p = atomicAdd(&g_cur[e], 1);
    g_idx[p] = n;
    int a = g_ape[n];
    p = atomicAdd(&g_cur[4 + a], 1);
    g_idx[p] = n;
}

// ---------------- lb loss ----------------
__global__ void lb_kernel(float* __restrict__ outp, long long i1)
{
    __shared__ float sh[256 * 9];
    int t = threadIdx.x;
    float u[8] = {0,0,0,0,0,0,0,0};
    float ms = 0.f;
    for (int n = t; n < NROW; n += 256) {
        u[g_cpe[n]]     += g_cm[n];
        u[4 + g_ape[n]] += g_am[n];
        ms += g_cm[n] + g_am[n];
    }
    #pragma unroll
    for (int j = 0; j < 8; j++) sh[t*9 + j] = u[j];
    sh[t*9 + 8] = ms;
    __syncthreads();
    for (int stride = 128; stride > 0; stride >>= 1) {
        if (t < stride)
            #pragma unroll
            for (int j = 0; j < 9; j++) sh[t*9 + j] += sh[(t + stride)*9 + j];
        __syncthreads();
    }
    if (t == 0 && i1 >= 0) {
        float denom = 4.0f * sh[8] + 1e-10f;
        float acc = 0.f;
        for (int j = 0; j < 8; j++) {
            float uu = sh[j] / denom;
            acc += uu * logf(uu + 1e-10f);
        }
        outp[i1] = acc / 8.0f;
    }
}

// ---------------- host launcher ----------------
static inline void cvtA(const float* src, __half* h, __half* l, long long n)
{
    int n4 = (int)(n / 4);
    cvt_a16<<<(n4 + 255)/256, 256>>>((const float4*)src, (uint2*)h, (uint2*)l, n4);
}
static inline void cvtW(const float* src, __half* d, long long n)
{
    int n4 = (int)(n / 4);
    cvt_w16<<<(n4 + 255)/256, 256>>>((const float4*)src, (uint2*)d, n4);
}

extern "C" void kernel_launch(void* const* d_in, const int* in_sizes, int n_in,
                              void* d_out, int out_size)
{
    const float* x        = (const float*)d_in[0];
    const float* timei    = (const float*)d_in[1];
    const float* caption  = (const float*)d_in[2];
    const float* acoustic = (const float*)d_in[3];
    const float* w_in     = (const float*)d_in[4];
    const float* b_in     = (const float*)d_in[5];
    const float* w_out    = (const float*)d_in[6];
    const float* b_out    = (const float*)d_in[7];
    const float* hlw      = (const float*)d_in[8];
    const float* hlb      = (const float*)d_in[9];
    const float* cgw      = (const float*)d_in[10];
    const float* cgb      = (const float*)d_in[11];
    const float* agw      = (const float*)d_in[12];
    const float* agb      = (const float*)d_in[13];
    const float* cw1      = (const float*)d_in[14];
    const float* cw2      = (const float*)d_in[15];
    const float* cw3      = (const float*)d_in[16];
    const float* aw1      = (const float*)d_in[17];
    const float* aw2      = (const float*)d_in[18];
    const float* aw3      = (const float*)d_in[19];
    const float* fw1      = (const float*)d_in[20];
    const float* fw2      = (const float*)d_in[21];
    const float* fw3      = (const float*)d_in[22];
    float* out = (float*)d_out;

    float *pq,*pk,*pv,*pca,*pcap2,*pclog,*palog,*phl,*pcm,*pam,*pH,*pR,*py;
    int *pidx,*poff,*pcnt;
    __half *xh,*xl,*gxh,*gxl,*cph,*cpl,*win16,*wout16,*ew16,*cah,*cal,*Hh,*Hl,*yh,*yl,*Rh,*Rl;

    cudaGetSymbolAddress((void**)&pq,    g_q);
    cudaGetSymbolAddress((void**)&pk,    g_k);
    cudaGetSymbolAddress((void**)&pv,    g_v);
    cudaGetSymbolAddress((void**)&pca,   g_ca);
    cudaGetSymbolAddress((void**)&pcap2, g_cap2);
    cudaGetSymbolAddress((void**)&pclog, g_caplog);
    cudaGetSymbolAddress((void**)&palog, g_aclog);
    cudaGetSymbolAddress((void**)&phl,   g_hl);
    cudaGetSymbolAddress((void**)&pcm,   g_cm);
    cudaGetSymbolAddress((void**)&pam,   g_am);
    cudaGetSymbolAddress((void**)&pH,    g_H);
    cudaGetSymbolAddress((void**)&pR,    g_R);
    cudaGetSymbolAddress((void**)&py,    g_y);
    cudaGetSymbolAddress((void**)&pidx,  g_idx);
    cudaGetSymbolAddress((void**)&poff,  g_off);
    cudaGetSymbolAddress((void**)&pcnt,  g_cnt);
    cudaGetSymbolAddress((void**)&xh,    g_xh);
    cudaGetSymbolAddress((void**)&xl,    g_xl);
    cudaGetSymbolAddress((void**)&gxh,   g_gxh);
    cudaGetSymbolAddress((void**)&gxl,   g_gxl);
    cudaGetSymbolAddress((void**)&cph,   g_caph);
    cudaGetSymbolAddress((void**)&cpl,   g_capl);
    cudaGetSymbolAddress((void**)&win16, g_win16);
    cudaGetSymbolAddress((void**)&wout16,g_wout16);
    cudaGetSymbolAddress((void**)&ew16,  g_ew16);
    cudaGetSymbolAddress((void**)&cah,   g_cah);
    cudaGetSymbolAddress((void**)&cal,   g_cal);
    cudaGetSymbolAddress((void**)&Hh,    g_Hh);
    cudaGetSymbolAddress((void**)&Hl,    g_Hl);
    cudaGetSymbolAddress((void**)&yh,    g_yh);
    cudaGetSymbolAddress((void**)&yl,    g_yl);
    cudaGetSymbolAddress((void**)&Rh,    g_Rh);
    cudaGetSymbolAddress((void**)&Rl,    g_Rl);

    cudaFuncSetAttribute(attn2, cudaFuncAttributeMaxDynamicSharedMemorySize, SMEM_ATTN);
    cudaFuncSetAttribute(gemm_cp<0,0,0>, cudaFuncAttributeMaxDynamicSharedMemorySize, GSM_SIZE);
    cudaFuncSetAttribute(gemm_cp<2,0,0>, cudaFuncAttributeMaxDynamicSharedMemorySize, GSM_SIZE);
    cudaFuncSetAttribute(gemm_cp<2,1,1>, cudaFuncAttributeMaxDynamicSharedMemorySize, GSM_SIZE);
    cudaFuncSetAttribute(gemm_cp<2,1,2>, cudaFuncAttributeMaxDynamicSharedMemorySize, GSM_SIZE);

    const int n4per = HDM/4;

    // conversions
    cvtA(x,       xh,  xl,  (long long)NROW*DM);
    cvtA(caption, cph, cpl, (long long)SKV*DM);
    cvtW(w_in,  win16,  3LL*DM*DM);
    cvtW(w_out, wout16, (long long)DM*DM);
    // Q/K/V projections
    gemm_cp<0,0,0><<<dim3(9,2,1),256,GSM_SIZE>>>(cph, cpl, DM, 0, win16 + (long long)DM*DM, DM, 0, b_in + DM,
        pk, DM, 0, nullptr,nullptr,nullptr,0, nullptr, SKV, DM, DM);
    gemm_cp<0,0,0><<<dim3(9,16,1),256,GSM_SIZE>>>(xh, xl, DM, 0, win16, DM, 0, b_in,
        pq, DM, 0, nullptr,nullptr,nullptr,0, nullptr, NROW, DM, DM);
    gemm_cp<0,0,0><<<dim3(9,2,1),256,GSM_SIZE>>>(cph, cpl, DM, 0, win16 + 2LL*DM*DM, DM, 0, b_in + 2*DM,
        pv, DM, 0, nullptr,nullptr,nullptr,0, nullptr, SKV, DM, DM);
    // attention
    attn2<<<dim3(16,8,2),256,SMEM_ATTN>>>(pq, pk, pv, pca);
    // out proj
    cvtA(pca, cah, cal, (long long)NROW*DM);
    gemm_cp<0,0,0><<<dim3(9,16,1),256,GSM_SIZE>>>(cah, cal, DM, 0, wout16, DM, 0, b_out,
        pcap2, DM, 0, nullptr,nullptr,nullptr,0, nullptr, NROW, DM, DM);
    // hl + gate logits (exact fp32)
    hlk<<<1,128>>>(timei, hlw, hlb, phl);
    gate4<<<NROW/8,256>>>(pcap2, cgw, cgb, pclog);
    gate4<<<NROW/8,256>>>(acoustic, agw, agb, palog);
    // gating + routing
    init_counts<<<1,32>>>();
    gating_kernel<<<8,256>>>(pclog, palog);
    offsets_kernel<<<1,1>>>();
    scatter_kernel<<<8,256>>>();
    // expert weight conversions into slots
    dim3 pg((n4per + 255)/256, 1, 4);
    cvt_pair16<<<pg,256>>>((const float4*)cw1, (const float4*)cw3, (uint2*)(ew16 + 0LL*HDM),  n4per);
    cvt_pair16<<<pg,256>>>((const float4*)aw1, (const float4*)aw3, (uint2*)(ew16 + 8LL*HDM),  n4per);
    cvtW(cw2, ew16 + 16LL*HDM, 4LL*HDM);
    cvtW(aw2, ew16 + 20LL*HDM, 4LL*HDM);
    cvt_pair16<<<pg,256>>>((const float4*)fw1, (const float4*)fw3, (uint2*)(ew16 + 24LL*HDM), n4per);
    cvtW(fw2, ew16 + 32LL*HDM, 4LL*HDM);
    // permute x rows into bucket order
    permute_x<<<2*NROW,128>>>((const uint4*)xh, (const uint4*)xl, (uint4*)gxh, (uint4*)gxl);
    // MoE up: one GEMM, z=8 buckets, N=1536 (h1|h3)
    gemm_cp<2,0,0><<<dim3(12,16,8),256,GSM_SIZE>>>(gxh, gxl, DM, 0,
        ew16, DM, 2LL*HDM, nullptr,
        pH, 1536, 0, nullptr, poff, pcnt, 0, nullptr, NROW, 1536, DM);
    silumul_pair16<<<(4096*192 + 255)/256,256>>>((const float4*)pH, (uint2*)Hh, (uint2*)Hl, 4096*192);
    // MoE down cap / ac
    gemm_cp<2,1,1><<<dim3(9,16,4),256,GSM_SIZE>>>(Hh, Hl, HIDN, 0,
        ew16 + 16LL*HDM, HIDN, (long long)HDM, nullptr,
        py, DM, 0, pidx, poff, pcnt, 0, pcm, NROW, DM, HIDN);
    gemm_cp<2,1,2><<<dim3(9,16,4),256,GSM_SIZE>>>(Hh, Hl, HIDN, 0,
        ew16 + 20LL*HDM, HIDN, (long long)HDM, nullptr,
        py, DM, 0, pidx, poff, pcnt, 4, pam, NROW, DM, HIDN);
    // region FF
    cvtA(py, yh, yl, (long long)NROW*DM);
    gemm_cp<0,0,0><<<dim3(12,16,4),256,GSM_SIZE>>>(yh, yl, DM, REG,
        ew16 + 24LL*HDM, DM, 2LL*HDM + REG, nullptr,
        pR, 1536, 2048LL*1536, nullptr,nullptr,nullptr,0, nullptr, NROW, 1536, REG);
    silumul_pair16<<<(8192*192 + 255)/256,256>>>((const float4*)pR, (uint2*)Rh, (uint2*)Rl, 8192*192);
    gemm_cp<0,0,0><<<dim3(3,16,4),256,GSM_SIZE>>>(Rh, Rl, HIDN, 2048LL*HIDN,
        ew16 + 32LL*HDM, HIDN, (long long)HDM + (long long)REG*HIDN, nullptr,
        out, DM, REG, nullptr,nullptr,nullptr,0, nullptr, NROW, REG, HIDN);
    // lb loss scalar
    long long zElems = (long long)NROW * DM;
    long long i1 = ((long long)out_size > zElems) ? zElems : -1;
    lb_kernel<<<1,256>>>(out, i1);
}

// round 11
// speedup vs baseline: 2.3003x; 1.0001x over previous
#include <cuda_runtime.h>
#include <cuda_fp16.h>
#include <cstdint>

#define NROW 2048
#define DM   1152
#define SKV  256
#define HIDN 768
#define REG  288            // DM/4
#define HDM  (HIDN*DM)      // one expert matrix (either orientation)

// ---------------- scratch (device globals; allocation-free) ----------------
__device__ float g_q[NROW*DM];
__device__ float g_k[SKV*DM];
__device__ float g_v[SKV*DM];
__device__ float g_cap2[NROW*DM];
__device__ float g_caplog[NROW*4];
__device__ float g_aclog[NROW*4];
__device__ float g_hl[4];
__device__ float g_cm[NROW];
__device__ float g_am[NROW];
__device__ int   g_cpe[NROW];
__device__ int   g_ape[NROW];
__device__ int   g_cnt[8];
__device__ int   g_off[8];
__device__ int   g_cur[8];
__device__ int   g_idx[2*NROW];          // perm position -> original row
__device__ float g_H[4096L*1536];        // MoE up combined (h1|h3), perm order
__device__ float g_R[8192L*1536];        // region up combined
__device__ float g_y[NROW*DM];

// fp16 operands: activations hi/lo (A side), weights single fp16 (B side)
__device__ __half g_xh[NROW*DM],  g_xl[NROW*DM];
__device__ __half g_gxh[2*NROW*DM], g_gxl[2*NROW*DM];
__device__ __half g_caph[SKV*DM], g_capl[SKV*DM];
__device__ __half g_win16[3*DM*DM];
__device__ __half g_wout16[DM*DM];
__device__ __half g_ew16[36L*HDM];
__device__ __half g_cah[NROW*DM], g_cal[NROW*DM];
__device__ __half g_Hh[4096L*HIDN], g_Hl[4096L*HIDN];
__device__ __half g_yh[NROW*DM],  g_yl[NROW*DM];
__device__ __half g_Rh[8192L*HIDN], g_Rl[8192L*HIDN];

// ---------------- helpers ----------------
__device__ __forceinline__ uint32_t smem_to_u32(const void* p) {
    uint32_t a;
    asm("{ .reg .u64 t; cvta.to.shared.u64 t, %1; cvt.u32.u64 %0, t; }" : "=r"(a) : "l"(p));
    return a;
}

#define CPA(dst, src, sz) \
    asm volatile("cp.async.cg.shared.global [%0], [%1], 16, %2;" \
                 :: "r"(dst), "l"(src), "r"(sz) : "memory")
#define CPA_COMMIT() asm volatile("cp.async.commit_group;" ::: "memory")
#define CPA_WAIT1()  asm volatile("cp.async.wait_group 1;" ::: "memory")
#define CPA_WAIT0()  asm volatile("cp.async.wait_group 0;" ::: "memory")

#define LDSM4(r0, r1, r2, r3, addr) \
    asm volatile("ldmatrix.sync.aligned.m8n8.x4.shared.b16 {%0,%1,%2,%3}, [%4];" \
                 : "=r"(r0), "=r"(r1), "=r"(r2), "=r"(r3) : "r"(addr))

__device__ __forceinline__ void mma16f(float* d, const uint32_t* a, const uint32_t* b)
{
    asm volatile(
        "mma.sync.aligned.m16n8k16.row.col.f32.f16.f16.f32 "
        "{%0,%1,%2,%3}, {%4,%5,%6,%7}, {%8,%9}, {%0,%1,%2,%3};\n"
        : "+f"(d[0]), "+f"(d[1]), "+f"(d[2]), "+f"(d[3])
        : "r"(a[0]), "r"(a[1]), "r"(a[2]), "r"(a[3]), "r"(b[0]), "r"(b[1]));
}

// ---------------- threefry2x32-20 (exact JAX, partitionable) ----------------
__device__ __forceinline__ uint32_t rotl32(uint32_t v, int r){ return (v<<r)|(v>>(32-r)); }

__device__ __forceinline__ void tf2x32(uint32_t k0, uint32_t k1, uint32_t x0, uint32_t x1,
                                       uint32_t& o0, uint32_t& o1)
{
    uint32_t ks2 = k0 ^ k1 ^ 0x1BD11BDAu;
    x0 += k0; x1 += k1;
#define TFR(r) { x0 += x1; x1 = rotl32(x1,(r)); x1 ^= x0; }
    TFR(13) TFR(15) TFR(26) TFR(6)   x0 += k1;  x1 += ks2 + 1u;
    TFR(17) TFR(29) TFR(16) TFR(24)  x0 += ks2; x1 += k0  + 2u;
    TFR(13) TFR(15) TFR(26) TFR(6)   x0 += k0;  x1 += k1  + 3u;
    TFR(17) TFR(29) TFR(16) TFR(24)  x0 += k1;  x1 += ks2 + 4u;
    TFR(13) TFR(15) TFR(26) TFR(6)   x0 += ks2; x1 += k0  + 5u;
#undef TFR
    o0 = x0; o1 = x1;
}

__device__ __forceinline__ uint32_t jax_bits_p(uint32_t k0, uint32_t k1, uint32_t i)
{
    uint32_t o0, o1;
    tf2x32(k0, k1, 0u, i, o0, o1);
    return o0 ^ o1;
}

__device__ __forceinline__ float gumbel_from_bits(uint32_t bits)
{
    uint32_t fb = (bits >> 9) | 0x3f800000u;
    float f = __uint_as_float(fb) - 1.0f;
    const float TINY = 1.17549435e-38f;
    float u = (f > 0.0f) ? f : TINY;
    return -logf(-logf(u));
}

// ---------------- conversion kernels ----------------
__device__ __forceinline__ void split4h(float4 f, uint2& hi, uint2& lo)
{
    __half2 h0 = __floats2half2_rn(f.x, f.y);
    __half2 h1 = __floats2half2_rn(f.z, f.w);
    float r0 = f.x - __half2float(__low2half(h0));
    float r1 = f.y - __half2float(__high2half(h0));
    float r2 = f.z - __half2float(__low2half(h1));
    float r3 = f.w - __half2float(__high2half(h1));
    __half2 l0 = __floats2half2_rn(r0, r1);
    __half2 l1 = __floats2half2_rn(r2, r3);
    hi = make_uint2(*(uint32_t*)&h0, *(uint32_t*)&h1);
    lo = make_uint2(*(uint32_t*)&l0, *(uint32_t*)&l1);
}

__device__ __forceinline__ uint2 pack4h(float4 f)
{
    __half2 h0 = __floats2half2_rn(f.x, f.y);
    __half2 h1 = __floats2half2_rn(f.z, f.w);
    return make_uint2(*(uint32_t*)&h0, *(uint32_t*)&h1);
}

__global__ void cvt_a16(const float4* __restrict__ src, uint2* __restrict__ hi,
                        uint2* __restrict__ lo, int n4)
{
    int i = blockIdx.x*blockDim.x + threadIdx.x;
    if (i >= n4) return;
    uint2 h, l;
    split4h(src[i], h, l);
    hi[i] = h; lo[i] = l;
}

__global__ void cvt_w16(const float4* __restrict__ src, uint2* __restrict__ dst, int n4)
{
    int i = blockIdx.x*blockDim.x + threadIdx.x;
    if (i >= n4) return;
    dst[i] = pack4h(src[i]);
}

__global__ void cvt_pair16(const float4* __restrict__ s1, const float4* __restrict__ s2,
                           uint2* __restrict__ dst, int n4per)
{
    int e = blockIdx.z;
    int i = blockIdx.x*blockDim.x + threadIdx.x;
    if (i >= n4per) return;
    dst[(long long)(2*e)*n4per + i]   = pack4h(s1[(long long)e*n4per + i]);
    dst[(long long)(2*e+1)*n4per + i] = pack4h(s2[(long long)e*n4per + i]);
}

__global__ void silumul_pair16(const float4* __restrict__ H, uint2* __restrict__ hi,
                               uint2* __restrict__ lo, int total)
{
    int i = blockIdx.x*blockDim.x + threadIdx.x;
    if (i >= total) return;
    int row = i / 192, j = i % 192;
    float4 a = H[(long long)row*384 + j];
    float4 c = H[(long long)row*384 + 192 + j];
    float4 r;
    r.x = a.x/(1.f+expf(-a.x))*c.x;
    r.y = a.y/(1.f+expf(-a.y))*c.y;
    r.z = a.z/(1.f+expf(-a.z))*c.z;
    r.w = a.w/(1.f+expf(-a.w))*c.w;
    uint2 h, l;
    split4h(r, h, l);
    hi[i] = h; lo[i] = l;
}

__global__ void permute_x(const uint4* __restrict__ xh, const uint4* __restrict__ xl,
                          uint4* __restrict__ gh, uint4* __restrict__ gl)
{
    const int W16 = DM*2/16;  // 144
    int p = blockIdx.x;
    int src = g_idx[p];
    for (int c = threadIdx.x; c < W16; c += blockDim.x) {
        gh[(long long)p*W16 + c] = xh[(long long)src*W16 + c];
        gl[(long long)p*W16 + c] = xl[(long long)src*W16 + c];
    }
}

// ---------------- fp16-split warp-MMA GEMM (2-term, 3-stage cp.async) -------
// Two-sweep inner loop: all independent ah*bh MMAs, then al*bh (dependency
// distance 16 >> HMMA latency). Per-accumulator op order unchanged.
// EPI: 0 store(+bias), 1 store*rowScale, 2 +=*rowScale, 3 = EPI2 + emit fp16 hi/lo.
#define STG 30720
#define GSM_SIZE (3*STG + 512)

template<int AMODE, int CMODE, int EPI>
__global__ __launch_bounds__(256)
void gemm_cp(const __half* __restrict__ Ah, const __half* __restrict__ Al,
             int lda, long long aOff,
             const __half* __restrict__ W, int ldw, long long wOff,
             const float* __restrict__ bias,
             float* __restrict__ C, int ldc, long long cOff,
             const int* __restrict__ rowIdx, const int* __restrict__ bOffA,
             const int* __restrict__ bCnt, int bBase,
             const float* __restrict__ rowScale,
             __half* __restrict__ Yh, __half* __restrict__ Yl,
             int M, int N, int K)
{
    extern __shared__ char smc[];
    const uint32_t smb = smem_to_u32(smc);
    int* rmap = (int*)(smc + 3*STG);

    const int e = blockIdx.z;
    Ah += (long long)e * aOff; Al += (long long)e * aOff;
    W  += (long long)e * wOff;
    C  += (long long)e * cOff;

    int rows = M, aBase = 0;
    if (AMODE == 2) { rows = bCnt[bBase+e]; aBase = bOffA[bBase+e]; }
    const int m0 = blockIdx.y * 128, n0 = blockIdx.x * 128;
    if (m0 >= rows) return;

    const int tid = threadIdx.x, warp = tid >> 5, lane = tid & 31;
    const int wm = warp & 3, wn = warp >> 2;

    if (CMODE == 1 && tid < 128) {
        int r = m0 + tid;
        rmap[tid] = (r < rows) ? rowIdx[aBase + r] : -1;
    }
    if (CMODE == 1) __syncthreads();

    const int lrow = tid >> 1;
    const int seg  = tid & 1;
    const bool av = (m0 + lrow) < rows;
    const long long arow = (long long)(aBase + m0 + lrow);
    const __half* aSrcH = Ah + (av ? arow * lda : 0) + seg*16;
    const __half* aSrcL = Al + (av ? arow * lda : 0) + seg*16;
    const uint32_t aSz = av ? 16u : 0u;
    const bool nok = (n0 + lrow) < N;
    const __half* bSrc = W + (nok ? (long long)(n0 + lrow) * ldw : 0) + seg*16;
    const uint32_t bSz = nok ? 16u : 0u;
    const uint32_t dRow = (uint32_t)lrow*80 + seg*32;

#define LOADS(c) { \
    const int k0 = (c)*32; \
    const uint32_t sb = smb + ((c)%3)*STG; \
    CPA(sb + dRow,              aSrcH + k0,     aSz); \
    CPA(sb + dRow + 16,         aSrcH + k0 + 8, aSz); \
    CPA(sb + 10240 + dRow,      aSrcL + k0,     aSz); \
    CPA(sb + 10240 + dRow + 16, aSrcL + k0 + 8, aSz); \
    CPA(sb + 20480 + dRow,      bSrc  + k0,     bSz); \
    CPA(sb + 20480 + dRow + 16, bSrc  + k0 + 8, bSz); \
    CPA_COMMIT(); }

    const uint32_t aoff = (uint32_t)(lane & 15)*80 + (((uint32_t)lane >> 4) << 4);
    const uint32_t boff = (uint32_t)((lane & 7) + ((lane >> 4) << 3))*80 + (uint32_t)(((lane >> 3) & 1) << 4);

    float d[2][8][4];
    #pragma unroll
    for (int i = 0; i < 2; i++)
        #pragma unroll
        for (int j = 0; j < 8; j++)
            #pragma unroll
            for (int r = 0; r < 4; r++) d[i][j][r] = 0.f;

#define COMPUTES(buf) { \
    const uint32_t sb = smb + (buf)*STG; \
    _Pragma("unroll") \
    for (int ks = 0; ks < 2; ks++) { \
        uint32_t ah[2][4], al[2][4], bh[4][4]; \
        _Pragma("unroll") \
        for (int mt = 0; mt < 2; mt++) { \
            uint32_t ad = sb + (uint32_t)(wm*32 + mt*16)*80 + ks*32 + aoff; \
            LDSM4(ah[mt][0], ah[mt][1], ah[mt][2], ah[mt][3], ad); \
            LDSM4(al[mt][0], al[mt][1], al[mt][2], al[mt][3], ad + 10240); \
        } \
        _Pragma("unroll") \
        for (int ng = 0; ng < 4; ng++) { \
            uint32_t bd = sb + 20480 + (uint32_t)(wn*64 + ng*16)*80 + ks*32 + boff; \
            LDSM4(bh[ng][0], bh[ng][1], bh[ng][2], bh[ng][3], bd); \
        } \
        _Pragma("unroll") \
        for (int mt = 0; mt < 2; mt++) \
            _Pragma("unroll") \
            for (int ng = 0; ng < 4; ng++) \
                _Pragma("unroll") \
                for (int h = 0; h < 2; h++) \
                    mma16f(d[mt][ng*2 + h], ah[mt], &bh[ng][2*h]); \
        _Pragma("unroll") \
        for (int mt = 0; mt < 2; mt++) \
            _Pragma("unroll") \
            for (int ng = 0; ng < 4; ng++) \
                _Pragma("unroll") \
                for (int h = 0; h < 2; h++) \
                    mma16f(d[mt][ng*2 + h], al[mt], &bh[ng][2*h]); \
    } }

    const int nc = K / 32;
    LOADS(0)
    if (nc > 1) LOADS(1)
    for (int c = 0; c < nc; c++) {
        if (c + 1 < nc) { CPA_WAIT1(); } else { CPA_WAIT0(); }
        __syncthreads();
        if (c + 2 < nc) LOADS(c+2)
        COMPUTES(c % 3)
    }
#undef LOADS
#undef COMPUTES

    // epilogue
    #pragma unroll
    for (int mt = 0; mt < 2; mt++) {
        #pragma unroll
        for (int h = 0; h < 2; h++) {
            int r = wm*32 + mt*16 + (lane >> 2) + 8*h;
            if (m0 + r >= rows) continue;
            int cr = (CMODE == 0) ? (aBase + m0 + r) : rmap[r];
            if (cr < 0) continue;
            float* crow = C + (long long)cr * ldc;
            float sc = (EPI >= 1) ? rowScale[cr] : 0.f;
            #pragma unroll
            for (int n8 = 0; n8 < 8; n8++) {
                int c0 = n0 + wn*64 + n8*8 + (lane & 3)*2;
                if (c0 >= N) continue;
                float v0 = d[mt][n8][2*h + 0];
                float v1 = d[mt][n8][2*h + 1];
                if (EPI == 0) {
                    if (bias) { v0 += bias[c0]; v1 += bias[c0+1]; }
                    *(float2*)(crow + c0) = make_float2(v0, v1);
                } else if (EPI == 1) {
                    *(float2*)(crow + c0) = make_float2(v0*sc, v1*sc);
                } else {
                    float2 o = *(float2*)(crow + c0);
                    float f0 = o.x + v0*sc, f1 = o.y + v1*sc;
                    *(float2*)(crow + c0) = make_float2(f0, f1);
                    if (EPI == 3) {
                        __half2 hh = __floats2half2_rn(f0, f1);
                        float r0 = f0 - __half2float(__low2half(hh));
                        float r1 = f1 - __half2float(__high2half(hh));
                        __half2 ll = __floats2half2_rn(r0, r1);
                        *(__half2*)(Yh + (long long)cr*ldc + c0) = hh;
                        *(__half2*)(Yl + (long long)cr*ldc + c0) = ll;
                    }
                }
            }
        }
    }
}

// ---------------- attention: 64 queries x (head,batch) per block ------------
// emits fp16 hi/lo split directly
#define SMEM_ATTN 220160

__global__ __launch_bounds__(256)
void attn2(const float* __restrict__ Q, const float* __restrict__ K,
           const float* __restrict__ V, __half* __restrict__ Oh, __half* __restrict__ Ol)
{
    extern __shared__ float smatt[];
    float* Qs = smatt;
    float* Ks = smatt + 144*64;
    float* Vs = smatt + 144*64 + 144*128;
    float* Ss = Vs + 128*148;

    const int tid = threadIdx.x;
    const int q0 = blockIdx.x * 64;
    const int h = blockIdx.y, b = blockIdx.z;
    const long long qrow0 = (long long)b*1024 + q0;
    const int hc = h*144;

    for (int i = tid; i < 64*36; i += 256) {
        int q = i / 36, f = i % 36;
        float4 v4 = *(const float4*)(Q + (qrow0 + q)*DM + hc + f*4);
        Qs[(f*4+0)*64+q]=v4.x; Qs[(f*4+1)*64+q]=v4.y;
        Qs[(f*4+2)*64+q]=v4.z; Qs[(f*4+3)*64+q]=v4.w;
    }
    for (int i = tid; i < 128*36; i += 256) {
        int k = i / 36, f = i % 36;
        float4 v4 = *(const float4*)(K + ((long long)b*128 + k)*DM + hc + f*4);
        Ks[(f*4+0)*128+k]=v4.x; Ks[(f*4+1)*128+k]=v4.y;
        Ks[(f*4+2)*128+k]=v4.z; Ks[(f*4+3)*128+k]=v4.w;
        float4 w4 = *(const float4*)(V + ((long long)b*128 + k)*DM + hc + f*4);
        *(float4*)&Vs[k*148 + f*4] = w4;
    }
    __syncthreads();

    const int tx = tid & 15, ty = tid >> 4;

    {
        float acc[4][8] = {};
        for (int d = 0; d < 144; d++) {
            float a[4], bv[8];
            *(float4*)a      = *(const float4*)&Qs[d*64 + ty*4];
            *(float4*)bv     = *(const float4*)&Ks[d*128 + tx*8];
            *(float4*)(bv+4) = *(const float4*)&Ks[d*128 + tx*8 + 4];
            #pragma unroll
            for (int i = 0; i < 4; i++)
                #pragma unroll
                for (int j = 0; j < 8; j++) acc[i][j] += a[i]*bv[j];
        }
        #pragma unroll
        for (int i = 0; i < 4; i++)
            #pragma unroll
            for (int j = 0; j < 8; j++)
                Ss[(ty*4+i)*132 + tx*8 + j] = acc[i][j] * (1.0f/12.0f);
    }
    __syncthreads();

    if (tid < 64) {
        float* r = Ss + tid*132;
        float mx = -1e30f;
        for (int k = 0; k < 128; k++) mx = fmaxf(mx, r[k]);
        float sum = 0.f;
        for (int k = 0; k < 128; k++) { float ev = expf(r[k]-mx); r[k] = ev; sum += ev; }
        float inv = 1.0f / sum;
        for (int k = 0; k < 128; k++) r[k] *= inv;
    }
    __syncthreads();

    {
        float o[4][9] = {};
        for (int k = 0; k < 128; k++) {
            float s[4];
            #pragma unroll
            for (int i = 0; i < 4; i++) s[i] = Ss[(ty*4+i)*132 + k];
            #pragma unroll
            for (int j = 0; j < 9; j++) {
                float vv = Vs[k*148 + tx*9 + j];
                #pragma unroll
                for (int i = 0; i < 4; i++) o[i][j] += s[i]*vv;
            }
        }
        #pragma unroll
        for (int i = 0; i < 4; i++)
            #pragma unroll
            for (int j = 0; j < 9; j++) {
                float v = o[i][j];
                __half hh = __float2half_rn(v);
                __half ll = __float2half_rn(v - __half2float(hh));
                long long off = (qrow0 + ty*4 + i)*DM + hc + tx*9 + j;
                Oh[off] = hh;
                Ol[off] = ll;
            }
    }
}

// ---------------- small exact kernels ----------------
__global__ void gate4(const float* __restrict__ A, const float* __restrict__ W,
                      const float* __restrict__ b, float* __restrict__ out)
{
    int w = blockIdx.x*8 + (threadIdx.x >> 5);
    int lane = threadIdx.x & 31;
    if (w >= NROW) return;
    const float* a = A + (long long)w*DM;
    float s0=0,s1=0,s2=0,s3=0;
    for (int c = lane*4; c < DM; c += 128) {
        float4 av = *(const float4*)(a + c);
        float4 w0 = *(const float4*)(W + c);
        float4 w1 = *(const float4*)(W + DM + c);
        float4 w2 = *(const float4*)(W + 2*DM + c);
        float4 w3 = *(const float4*)(W + 3*DM + c);
        s0 += av.x*w0.x + av.y*w0.y + av.z*w0.z + av.w*w0.w;
        s1 += av.x*w1.x + av.y*w1.y + av.z*w1.z + av.w*w1.w;
        s2 += av.x*w2.x + av.y*w2.y + av.z*w2.z + av.w*w2.w;
        s3 += av.x*w3.x + av.y*w3.y + av.z*w3.z + av.w*w3.w;
    }
    #pragma unroll
    for (int o = 16; o > 0; o >>= 1) {
        s0 += __shfl_xor_sync(0xffffffffu, s0, o);
        s1 += __shfl_xor_sync(0xffffffffu, s1, o);
        s2 += __shfl_xor_sync(0xffffffffu, s2, o);
        s3 += __shfl_xor_sync(0xffffffffu, s3, o);
    }
    if (lane == 0) {
        out[w*4+0] = s0 + b[0]; out[w*4+1] = s1 + b[1];
        out[w*4+2] = s2 + b[2]; out[w*4+3] = s3 + b[3];
    }
}

__global__ void hlk(const float* __restrict__ t, const float* __restrict__ w,
                    const float* __restrict__ bb, float* __restrict__ hl)
{
    int wi = threadIdx.x >> 5, lane = threadIdx.x & 31;
    int r = wi >> 1, o = wi & 1;
    const float* a = t + r*DM;
    const float* ww = w + o*DM;
    float s = 0.f;
    for (int c = lane*4; c < DM; c += 128) {
        float4 av = *(const float4*)(a + c);
        float4 wv = *(const float4*)(ww + c);
        s += av.x*wv.x + av.y*wv.y + av.z*wv.z + av.w*wv.w;
    }
    #pragma unroll
    for (int off = 16; off > 0; off >>= 1) s += __shfl_xor_sync(0xffffffffu, s, off);
    if (lane == 0) hl[r*2+o] = s + bb[o];
}

// ---------------- gating + routing ----------------
__global__ void init_counts()
{
    if (threadIdx.x < 8) g_cnt[threadIdx.x] = 0;
}

__global__ void gating_kernel(const float* __restrict__ caplog, const float* __restrict__ aclog)
{
    int n = blockIdx.x * blockDim.x + threadIdx.x;
    if (n >= NROW) return;

    uint32_t k1a,k1b,k2a,k2b,k3a,k3b;
    tf2x32(0u, 42u, 0u, 0u, k1a, k1b);
    tf2x32(0u, 42u, 0u, 1u, k2a, k2b);
    tf2x32(0u, 42u, 0u, 2u, k3a, k3b);

    float g0 = gumbel_from_bits(jax_bits_p(k1a, k1b, 2u*(uint32_t)n + 0u));
    float g1 = gumbel_from_bits(jax_bits_p(k1a, k1b, 2u*(uint32_t)n + 1u));
    int bb = n >> 10;
    float l0 = g_hl[2*bb + 0] + g0;
    float l1 = g_hl[2*bb + 1] + g1;
    float mx = fmaxf(l0, l1);
    float e0 = expf(l0 - mx), e1 = expf(l1 - mx);
    float inv = 1.0f / (e0 + e1);
    g_cm[n] = e0 * inv;
    g_am[n] = e1 * inv;

    int be = 0; float bv = -1e30f;
    #pragma unroll
    for (int c = 0; c < 4; c++) {
        float g = gumbel_from_bits(jax_bits_p(k2a, k2b, 4u*(uint32_t)n + (uint32_t)c));
        float yv = caplog[n*4 + c] + g;
        if (yv > bv) { bv = yv; be = c; }
    }
    g_cpe[n] = be;
    atomicAdd(&g_cnt[be], 1);

    int ae = 0; bv = -1e30f;
    #pragma unroll
    for (int c = 0; c < 4; c++) {
        float g = gumbel_from_bits(jax_bits_p(k3a, k3b, 4u*(uint32_t)n + (uint32_t)c));
        float yv = aclog[n*4 + c] + g;
        if (yv > bv) { bv = yv; ae = c; }
    }
    g_ape[n] = ae;
    atomicAdd(&g_cnt[4 + ae], 1);
}

__global__ void offsets_kernel()
{
    int o = 0;
    for (int e = 0; e < 4; e++) { g_off[e] = o; o += g_cnt[e]; }
    o = NROW;
    for (int e = 4; e < 8; e++) { g_off[e] = o; o += g_cnt[e]; }
    for (int j = 0; j < 8; j++) g_cur[j] = g_off[j];
}

__global__ void scatter_kernel()
{
    int n = blockIdx.x * blockDim.x + threadIdx.x;
    if (n >= NROW) return;
    int e = g_cpe[n];
    int p = atomicAdd(&g_cur[e], 1);
    g_idx[p] = n;
    int a = g_ape[n];
    p = atomicAdd(&g_cur[4 + a], 1);
    g_idx[p] = n;
}

// ---------------- lb loss ----------------
__global__ void lb_kernel(float* __restrict__ outp, long long i1)
{
    __shared__ float sh[256 * 9];
    int t = threadIdx.x;
    float u[8] = {0,0,0,0,0,0,0,0};
    float ms = 0.f;
    for (int n = t; n < NROW; n += 256) {
        u[g_cpe[n]]     += g_cm[n];
        u[4 + g_ape[n]] += g_am[n];
        ms += g_cm[n] + g_am[n];
    }
    #pragma unroll
    for (int j = 0; j < 8; j++) sh[t*9 + j] = u[j];
    sh[t*9 + 8] = ms;
    __syncthreads();
    for (int stride = 128; stride > 0; stride >>= 1) {
        if (t < stride)
            #pragma unroll
            for (int j = 0; j < 9; j++) sh[t*9 + j] += sh[(t + stride)*9 + j];
        __syncthreads();
    }
    if (t == 0 && i1 >= 0) {
        float denom = 4.0f * sh[8] + 1e-10f;
        float acc = 0.f;
        for (int j = 0; j < 8; j++) {
            float uu = sh[j] / denom;
            acc += uu * logf(uu + 1e-10f);
        }
        outp[i1] = acc / 8.0f;
    }
}

// ---------------- host launcher ----------------
static inline void cvtA(const float* src, __half* h, __half* l, long long n)
{
    int n4 = (int)(n / 4);
    cvt_a16<<<(n4 + 255)/256, 256>>>((const float4*)src, (uint2*)h, (uint2*)l, n4);
}
static inline void cvtW(const float* src, __half* d, long long n)
{
    int n4 = (int)(n / 4);
    cvt_w16<<<(n4 + 255)/256, 256>>>((const float4*)src, (uint2*)d, n4);
}

extern "C" void kernel_launch(void* const* d_in, const int* in_sizes, int n_in,
                              void* d_out, int out_size)
{
    const float* x        = (const float*)d_in[0];
    const float* timei    = (const float*)d_in[1];
    const float* caption  = (const float*)d_in[2];
    const float* acoustic = (const float*)d_in[3];
    const float* w_in     = (const float*)d_in[4];
    const float* b_in     = (const float*)d_in[5];
    const float* w_out    = (const float*)d_in[6];
    const float* b_out    = (const float*)d_in[7];
    const float* hlw      = (const float*)d_in[8];
    const float* hlb      = (const float*)d_in[9];
    const float* cgw      = (const float*)d_in[10];
    const float* cgb      = (const float*)d_in[11];
    const float* agw      = (const float*)d_in[12];
    const float* agb      = (const float*)d_in[13];
    const float* cw1      = (const float*)d_in[14];
    const float* cw2      = (const float*)d_in[15];
    const float* cw3      = (const float*)d_in[16];
    const float* aw1      = (const float*)d_in[17];
    const float* aw2      = (const float*)d_in[18];
    const float* aw3      = (const float*)d_in[19];
    const float* fw1      = (const float*)d_in[20];
    const float* fw2      = (const float*)d_in[21];
    const float* fw3      = (const float*)d_in[22];
    float* out = (float*)d_out;

    float *pq,*pk,*pv,*pcap2,*pclog,*palog,*phl,*pcm,*pam,*pH,*pR,*py;
    int *pidx,*poff,*pcnt;
    __half *xh,*xl,*gxh,*gxl,*cph,*cpl,*win16,*wout16,*ew16,*cah,*cal,*Hh,*Hl,*yh,*yl,*Rh,*Rl;

    cudaGetSymbolAddress((void**)&pq,    g_q);
    cudaGetSymbolAddress((void**)&pk,    g_k);
    cudaGetSymbolAddress((void**)&pv,    g_v);
    cudaGetSymbolAddress((void**)&pcap2, g_cap2);
    cudaGetSymbolAddress((void**)&pclog, g_caplog);
    cudaGetSymbolAddress((void**)&palog, g_aclog);
    cudaGetSymbolAddress((void**)&phl,   g_hl);
    cudaGetSymbolAddress((void**)&pcm,   g_cm);
    cudaGetSymbolAddress((void**)&pam,   g_am);
    cudaGetSymbolAddress((void**)&pH,    g_H);
    cudaGetSymbolAddress((void**)&pR,    g_R);
    cudaGetSymbolAddress((void**)&py,    g_y);
    cudaGetSymbolAddress((void**)&pidx,  g_idx);
    cudaGetSymbolAddress((void**)&poff,  g_off);
    cudaGetSymbolAddress((void**)&pcnt,  g_cnt);
    cudaGetSymbolAddress((void**)&xh,    g_xh);
    cudaGetSymbolAddress((void**)&xl,    g_xl);
    cudaGetSymbolAddress((void**)&gxh,   g_gxh);
    cudaGetSymbolAddress((void**)&gxl,   g_gxl);
    cudaGetSymbolAddress((void**)&cph,   g_caph);
    cudaGetSymbolAddress((void**)&cpl,   g_capl);
    cudaGetSymbolAddress((void**)&win16, g_win16);
    cudaGetSymbolAddress((void**)&wout16,g_wout16);
    cudaGetSymbolAddress((void**)&ew16,  g_ew16);
    cudaGetSymbolAddress((void**)&cah,   g_cah);
    cudaGetSymbolAddress((void**)&cal,   g_cal);
    cudaGetSymbolAddress((void**)&Hh,    g_Hh);
    cudaGetSymbolAddress((void**)&Hl,    g_Hl);
    cudaGetSymbolAddress((void**)&yh,    g_yh);
    cudaGetSymbolAddress((void**)&yl,    g_yl);
    cudaGetSymbolAddress((void**)&Rh,    g_Rh);
    cudaGetSymbolAddress((void**)&Rl,    g_Rl);

    cudaFuncSetAttribute(attn2, cudaFuncAttributeMaxDynamicSharedMemorySize, SMEM_ATTN);
    cudaFuncSetAttribute(gemm_cp<0,0,0>, cudaFuncAttributeMaxDynamicSharedMemorySize, GSM_SIZE);
    cudaFuncSetAttribute(gemm_cp<2,0,0>, cudaFuncAttributeMaxDynamicSharedMemorySize, GSM_SIZE);
    cudaFuncSetAttribute(gemm_cp<2,1,1>, cudaFuncAttributeMaxDynamicSharedMemorySize, GSM_SIZE);
    cudaFuncSetAttribute(gemm_cp<2,1,3>, cudaFuncAttributeMaxDynamicSharedMemorySize, GSM_SIZE);

    const int n4per = HDM/4;

    // [1] cvtA(x)  [2] cvtW(w_in)  [3] cvtA(caption)  [4] gemm Q  <- profiled slot
    cvtA(x, xh, xl, (long long)NROW*DM);
    cvtW(w_in, win16, 3LL*DM*DM);
    cvtA(caption, cph, cpl, (long long)SKV*DM);
    gemm_cp<0,0,0><<<dim3(9,16,1),256,GSM_SIZE>>>(xh, xl, DM, 0, win16, DM, 0, b_in,
        pq, DM, 0, nullptr,nullptr,nullptr,0, nullptr, nullptr, nullptr, NROW, DM, DM);
    gemm_cp<0,0,0><<<dim3(9,2,1),256,GSM_SIZE>>>(cph, cpl, DM, 0, win16 + (long long)DM*DM, DM, 0, b_in + DM,
        pk, DM, 0, nullptr,nullptr,nullptr,0, nullptr, nullptr, nullptr, SKV, DM, DM);
    gemm_cp<0,0,0><<<dim3(9,2,1),256,GSM_SIZE>>>(cph, cpl, DM, 0, win16 + 2LL*DM*DM, DM, 0, b_in + 2*DM,
        pv, DM, 0, nullptr,nullptr,nullptr,0, nullptr, nullptr, nullptr, SKV, DM, DM);
    cvtW(w_out, wout16, (long long)DM*DM);
    // attention -> fp16 hi/lo directly
    attn2<<<dim3(16,8,2),256,SMEM_ATTN>>>(pq, pk, pv, cah, cal);
    // out proj
    gemm_cp<0,0,0><<<dim3(9,16,1),256,GSM_SIZE>>>(cah, cal, DM, 0, wout16, DM, 0, b_out,
        pcap2, DM, 0, nullptr,nullptr,nullptr,0, nullptr, nullptr, nullptr, NROW, DM, DM);
    // hl + gate logits (exact fp32)
    hlk<<<1,128>>>(timei, hlw, hlb, phl);
    gate4<<<NROW/8,256>>>(pcap2, cgw, cgb, pclog);
    gate4<<<NROW/8,256>>>(acoustic, agw, agb, palog);
    // gating + routing
    init_counts<<<1,32>>>();
    gating_kernel<<<8,256>>>(pclog, palog);
    offsets_kernel<<<1,1>>>();
    scatter_kernel<<<8,256>>>();
    // expert weight conversions into slots
    dim3 pg((n4per + 255)/256, 1, 4);
    cvt_pair16<<<pg,256>>>((const float4*)cw1, (const float4*)cw3, (uint2*)(ew16 + 0LL*HDM),  n4per);
    cvt_pair16<<<pg,256>>>((const float4*)aw1, (const float4*)aw3, (uint2*)(ew16 + 8LL*HDM),  n4per);
    cvtW(cw2, ew16 + 16LL*HDM, 4LL*HDM);
    cvtW(aw2, ew16 + 20LL*HDM, 4LL*HDM);
    cvt_pair16<<<pg,256>>>((const float4*)fw1, (const float4*)fw3, (uint2*)(ew16 + 24LL*HDM), n4per);
    cvtW(fw2, ew16 + 32LL*HDM, 4LL*HDM);
    // permute x rows into bucket order
    permute_x<<<2*NROW,128>>>((const uint4*)xh, (const uint4*)xl, (uint4*)gxh, (uint4*)gxl);
    // MoE up: one GEMM, z=8 buckets, N=1536 (h1|h3)
    gemm_cp<2,0,0><<<dim3(12,16,8),256,GSM_SIZE>>>(gxh, gxl, DM, 0,
        ew16, DM, 2LL*HDM, nullptr,
        pH, 1536, 0, nullptr, poff, pcnt, 0, nullptr, nullptr, nullptr, NROW, 1536, DM);
    silumul_pair16<<<(4096*192 + 255)/256,256>>>((const float4*)pH, (uint2*)Hh, (uint2*)Hl, 4096*192);
    // MoE down cap / ac (ac emits yh/yl split in epilogue)
    gemm_cp<2,1,1><<<dim3(9,16,4),256,GSM_SIZE>>>(Hh, Hl, HIDN, 0,
        ew16 + 16LL*HDM, HIDN, (long long)HDM, nullptr,
        py, DM, 0, pidx, poff, pcnt, 0, pcm, nullptr, nullptr, NROW, DM, HIDN);
    gemm_cp<2,1,3><<<dim3(9,16,4),256,GSM_SIZE>>>(Hh, Hl, HIDN, 0,
        ew16 + 20LL*HDM, HIDN, (long long)HDM, nullptr,
        py, DM, 0, pidx, poff, pcnt, 4, pam, yh, yl, NROW, DM, HIDN);
    // region FF
    gemm_cp<0,0,0><<<dim3(12,16,4),256,GSM_SIZE>>>(yh, yl, DM, REG,
        ew16 + 24LL*HDM, DM, 2LL*HDM + REG, nullptr,
        pR, 1536, 2048LL*1536, nullptr,nullptr,nullptr,0, nullptr, nullptr, nullptr, NROW, 1536, REG);
    silumul_pair16<<<(8192*192 + 255)/256,256>>>((const float4*)pR, (uint2*)Rh, (uint2*)Rl, 8192*192);
    gemm_cp<0,0,0><<<dim3(3,16,4),256,GSM_SIZE>>>(Rh, Rl, HIDN, 2048LL*HIDN,
        ew16 + 32LL*HDM, HIDN, (long long)HDM + (long long)REG*HIDN, nullptr,
        out, DM, REG, nullptr,nullptr,nullptr,0, nullptr, nullptr, nullptr, NROW, REG, HIDN);
    // lb loss scalar
    long long zElems = (long long)NROW * DM;
    long long i1 = ((long long)out_size > zElems) ? zElems : -1;
    lb_kernel<<<1,256>>>(out, i1);
}